// round 5
// baseline (speedup 1.0000x reference)
#include <cuda_runtime.h>
#include <cuda_bf16.h>
#include <math.h>

#define HD      256
#define AD      64
#define VOCAB   32000
#define TS      64
#define BB      32
#define SQ      1024
#define H2      512
#define ROWS_TOT (TS*BB)   /* 2048 */

// ---------------- scratch: static device globals (no allocation) ----------------
__device__ float g_embT[TS*HD*BB];                 // [t][i][b]
__device__ float g_hT[2*HD*BB];                    // ping-pong [p][k][b]
__device__ float g_ctxT[2*HD*BB];                  // ping-pong [p][h][b]
__device__ float g_c2[(size_t)BB*AD*SQ];           // [b][a][s]
__device__ float g_attw[BB*SQ];                    // [b][s]
__device__ float g_obuf[(size_t)ROWS_TOT*H2];      // [t*B+b][0:256 h | 256:512 ctx]
__device__ float g_q[(size_t)ROWS_TOT*HD];         // fc1 output
__device__ float g_f1w1T[HD*HD];
__device__ float g_f1w2T[HD*AD];
__device__ float g_f2w1T[HD*HD];
__device__ float g_f2w2T[HD*AD];
__device__ float g_fc1wT[H2*HD];
__device__ float g_fc2wT[(size_t)HD*VOCAB];        // [k][n]
__device__ float g_nll[ROWS_TOT];
__device__ float g_msk[ROWS_TOT];

// packed f32x2 fma (sm_103a)
__device__ __forceinline__ float2 ffma2(float2 a, float2 b, float2 c) {
    union U { float2 f; unsigned long long u; };
    U ua, ub, uc, ud;
    ua.f = a; ub.f = b; uc.f = c;
    asm("fma.rn.f32x2 %0, %1, %2, %3;" : "=l"(ud.u) : "l"(ua.u), "l"(ub.u), "l"(uc.u));
    return ud.f;
}

// ---------------- prep ----------------
__global__ void k_zero() {
    int i = blockIdx.x * blockDim.x + threadIdx.x;
    if (i < 2*HD*BB) { g_hT[i] = 0.f; g_ctxT[i] = 0.f; }
}

// dst[c*rows + r] = src[r*cols + c]
__global__ void k_transpose(const float* __restrict__ src, int dst_id, int rows, int cols) {
    float* dst = (dst_id == 0) ? g_f1w1T : (dst_id == 1) ? g_f1w2T :
                 (dst_id == 2) ? g_f2w1T : (dst_id == 3) ? g_f2w2T :
                 (dst_id == 4) ? g_fc1wT : g_fc2wT;
    __shared__ float tile[32][33];
    int c0 = blockIdx.x * 32, r0 = blockIdx.y * 32;
    int tx = threadIdx.x, ty = threadIdx.y;
    for (int j = ty; j < 32; j += 8) {
        int r = r0 + j, c = c0 + tx;
        if (r < rows && c < cols) tile[j][tx] = src[(size_t)r*cols + c];
    }
    __syncthreads();
    for (int j = ty; j < 32; j += 8) {
        int r = r0 + tx, c = c0 + j;
        if (r < rows && c < cols) dst[(size_t)c*rows + r] = tile[tx][j];
    }
}

__global__ void k_embT(const int* __restrict__ yin, const float* __restrict__ emb) {
    int t = blockIdx.x, i = threadIdx.x;
    for (int b = 0; b < BB; b++) {
        int row = yin[t*BB + b];
        g_embT[((size_t)t*HD + i)*BB + b] = emb[(size_t)row*HD + i];
    }
}

// ---------------- c2 = tanh(relu(y_enc @ f2w1^T + b1) @ f2w2^T + b2), stored [b][a][s] ----
__global__ void k_c2(const float* __restrict__ yenc,
                     const float* __restrict__ b1, const float* __restrict__ b2) {
    __shared__ float2 ysp[HD][8];     // [i][row-pair]  16KB
    __shared__ float  hid[16][HD];    // 16KB
    int r0 = blockIdx.x * 16;
    int tid = threadIdx.x;
    float* ysf = (float*)ysp;         // viewed as [i][16] floats
    for (int idx = tid; idx < 16*HD; idx += 256) {
        int r = idx >> 8, i = idx & 255;
        ysf[i*16 + r] = yenc[(size_t)(r0 + r)*HD + i];
    }
    __syncthreads();
    {   // layer 1: thread j computes 16 rows
        int j = tid;
        float bj = b1[j];
        float2 acc[8];
        #pragma unroll
        for (int p = 0; p < 8; p++) acc[p] = make_float2(bj, bj);
        for (int i = 0; i < HD; i++) {
            float w = g_f2w1T[i*HD + j];
            float2 wp = make_float2(w, w);
            #pragma unroll
            for (int p = 0; p < 8; p++) acc[p] = ffma2(wp, ysp[i][p], acc[p]);
        }
        #pragma unroll
        for (int p = 0; p < 8; p++) {
            hid[2*p][j]   = fmaxf(acc[p].x, 0.f);
            hid[2*p+1][j] = fmaxf(acc[p].y, 0.f);
        }
    }
    __syncthreads();
    #pragma unroll
    for (int q = 0; q < 4; q++) {
        int o = tid + q*256;              // 16 rows x 64 a
        int rr = o >> 6, a = o & 63;
        float acc = b2[a];
        for (int i = 0; i < HD; i++) acc = fmaf(hid[rr][i], g_f2w2T[i*AD + a], acc);
        int gr = r0 + rr;                 // gr = s*32 + b
        int s = gr >> 5, b = gr & 31;
        g_c2[((size_t)b*AD + a)*SQ + s] = tanhf(acc);
    }
}

// ---------------- GRU step: 128 blocks x 256 threads, 2 k's per block ----------------
__global__ void k_gru(int t,
                      const float* __restrict__ wih, const float* __restrict__ bih,
                      const float* __restrict__ whh, const float* __restrict__ bhh) {
    __shared__ float red[2][4][6][32];
    int tid = threadIdx.x;
    int lane = tid & 31, seg = (tid >> 5) & 3, kk = tid >> 7;
    int k = blockIdx.x*2 + kk;
    const float* embt = g_embT + (size_t)t*HD*BB;
    const float* ctxt = g_ctxT + (size_t)(t & 1)*HD*BB;
    const float* ht   = g_hT   + (size_t)(t & 1)*HD*BB;
    const float* wr = wih + (size_t)k*H2;
    const float* wz = wih + (size_t)(HD + k)*H2;
    const float* wn = wih + (size_t)(2*HD + k)*H2;
    float a_r = 0.f, a_z = 0.f, a_n = 0.f;
    int ibase = seg*128;
    const float* xp = (seg < 2) ? (embt + (size_t)ibase*BB + lane)
                                : (ctxt + (size_t)(ibase - 256)*BB + lane);
    #pragma unroll 4
    for (int ii = 0; ii < 128; ii++) {
        float x = xp[(size_t)ii*BB];
        int i = ibase + ii;
        a_r = fmaf(wr[i], x, a_r);
        a_z = fmaf(wz[i], x, a_z);
        a_n = fmaf(wn[i], x, a_n);
    }
    const float* vr = whh + (size_t)k*HD;
    const float* vz = whh + (size_t)(HD + k)*HD;
    const float* vn = whh + (size_t)(2*HD + k)*HD;
    float b_r = 0.f, b_z = 0.f, b_n = 0.f;
    int jbase = seg*64;
    const float* hp = ht + (size_t)jbase*BB + lane;
    #pragma unroll 4
    for (int ii = 0; ii < 64; ii++) {
        float hv = hp[(size_t)ii*BB];
        int i = jbase + ii;
        b_r = fmaf(vr[i], hv, b_r);
        b_z = fmaf(vz[i], hv, b_z);
        b_n = fmaf(vn[i], hv, b_n);
    }
    red[kk][seg][0][lane] = a_r; red[kk][seg][1][lane] = a_z; red[kk][seg][2][lane] = a_n;
    red[kk][seg][3][lane] = b_r; red[kk][seg][4][lane] = b_z; red[kk][seg][5][lane] = b_n;
    __syncthreads();
    if (tid < 64) {
        int kk2 = tid >> 5, ln = tid & 31;
        int k2 = blockIdx.x*2 + kk2;
        float s[6];
        #pragma unroll
        for (int g = 0; g < 6; g++)
            s[g] = red[kk2][0][g][ln] + red[kk2][1][g][ln] + red[kk2][2][g][ln] + red[kk2][3][g][ln];
        float gr_ = s[0] + bih[k2]      + s[3] + bhh[k2];
        float gz_ = s[1] + bih[HD + k2] + s[4] + bhh[HD + k2];
        float r = 1.f / (1.f + expf(-gr_));
        float z = 1.f / (1.f + expf(-gz_));
        float n = tanhf((s[2] + bih[2*HD + k2]) + r*(s[5] + bhh[2*HD + k2]));
        float hprev = g_hT[(size_t)(t & 1)*HD*BB + (size_t)k2*BB + ln];
        float hn = (1.f - z)*n + z*hprev;
        g_hT[(size_t)((t + 1) & 1)*HD*BB + (size_t)k2*BB + ln] = hn;
        g_obuf[(size_t)(t*BB + ln)*H2 + k2] = hn;
    }
}

// ---------------- attention: c1 + scores + softmax (one block per batch) ----------------
__global__ void k_attn(int t, const float* __restrict__ f1b1, const float* __restrict__ f1b2) {
    __shared__ float hsm[HD];
    __shared__ float hid[HD];
    __shared__ float c1s[AD];
    __shared__ float rsh[8];
    __shared__ float s_mx, s_sum;
    int b = blockIdx.x, tid = threadIdx.x;
    const float* hT = g_hT + (size_t)((t + 1) & 1)*HD*BB;
    hsm[tid] = hT[(size_t)tid*BB + b];
    __syncthreads();
    {   // hidden = relu(f1w1 @ h + b1)
        float acc = f1b1[tid];
        for (int i = 0; i < HD; i++) acc = fmaf(g_f1w1T[i*HD + tid], hsm[i], acc);
        hid[tid] = fmaxf(acc, 0.f);
    }
    __syncthreads();
    if (tid < AD) {
        float acc = f1b2[tid];
        for (int i = 0; i < HD; i++) acc = fmaf(g_f1w2T[i*AD + tid], hid[i], acc);
        c1s[tid] = tanhf(acc);
    }
    __syncthreads();
    // scores: 4 s-values per thread
    const float* c2b = g_c2 + (size_t)b*AD*SQ;
    float sc[4];
    float mloc = -1e30f;
    #pragma unroll
    for (int q = 0; q < 4; q++) {
        int s = tid + q*256;
        float acc = 0.f;
        #pragma unroll 4
        for (int a = 0; a < AD; a++) acc = fmaf(c1s[a], c2b[(size_t)a*SQ + s], acc);
        sc[q] = acc;
        mloc = fmaxf(mloc, acc);
    }
    // block max
    #pragma unroll
    for (int o = 16; o; o >>= 1) mloc = fmaxf(mloc, __shfl_xor_sync(0xffffffffu, mloc, o));
    if ((tid & 31) == 0) rsh[tid >> 5] = mloc;
    __syncthreads();
    if (tid == 0) {
        float v = rsh[0];
        for (int w = 1; w < 8; w++) v = fmaxf(v, rsh[w]);
        s_mx = v;
    }
    __syncthreads();
    float mx = s_mx;
    float sloc = 0.f;
    #pragma unroll
    for (int q = 0; q < 4; q++) { sc[q] = __expf(sc[q] - mx); sloc += sc[q]; }
    #pragma unroll
    for (int o = 16; o; o >>= 1) sloc += __shfl_xor_sync(0xffffffffu, sloc, o);
    if ((tid & 31) == 0) rsh[tid >> 5] = sloc;
    __syncthreads();
    if (tid == 0) {
        float v = 0.f;
        for (int w = 0; w < 8; w++) v += rsh[w];
        s_sum = v;
    }
    __syncthreads();
    float inv = 1.f / s_sum;
    #pragma unroll
    for (int q = 0; q < 4; q++) g_attw[b*SQ + tid + q*256] = sc[q] * inv;
}

// ---------------- ctx = attw @ y_enc : grid (32 b, 8 h-chunks), 128 threads ----------------
__global__ void k_ctx(int t, const float* __restrict__ yenc) {
    __shared__ float red[4][32];
    int b = blockIdx.x, hc = blockIdx.y;
    int tid = threadIdx.x, wi = tid >> 5, lane = tid & 31;
    int h = hc*32 + lane;
    const float* aw = g_attw + b*SQ;
    float acc = 0.f;
    int s0 = wi*256;
    #pragma unroll 4
    for (int ii = 0; ii < 256; ii++) {
        int s = s0 + ii;
        acc = fmaf(aw[s], yenc[((size_t)s*BB + b)*HD + h], acc);
    }
    red[wi][lane] = acc;
    __syncthreads();
    if (tid < 32) {
        int hh = hc*32 + tid;
        float v = red[0][tid] + red[1][tid] + red[2][tid] + red[3][tid];
        g_ctxT[(size_t)((t + 1) & 1)*HD*BB + (size_t)hh*BB + b] = v;
        g_obuf[(size_t)(t*BB + b)*H2 + HD + hh] = v;
    }
}

// ---------------- fc1: q = relu(obuf @ fc1_w^T + b), 16 rows/block ----------------
__global__ void k_fc1(const float* __restrict__ fc1b) {
    __shared__ float2 xsp[H2][8];     // 32KB
    int r0 = blockIdx.x * 16;
    int tid = threadIdx.x;
    float* xsf = (float*)xsp;
    for (int idx = tid; idx < 16*H2; idx += 256) {
        int r = idx >> 9, i = idx & 511;
        xsf[i*16 + r] = g_obuf[(size_t)(r0 + r)*H2 + i];
    }
    __syncthreads();
    int j = tid;
    float bj = fc1b[j];
    float2 acc[8];
    #pragma unroll
    for (int p = 0; p < 8; p++) acc[p] = make_float2(bj, bj);
    for (int i = 0; i < H2; i++) {
        float w = g_fc1wT[i*HD + j];
        float2 wp = make_float2(w, w);
        #pragma unroll
        for (int p = 0; p < 8; p++) acc[p] = ffma2(wp, xsp[i][p], acc[p]);
    }
    #pragma unroll
    for (int p = 0; p < 8; p++) {
        g_q[(size_t)(r0 + 2*p)*HD + j]     = fmaxf(acc[p].x, 0.f);
        g_q[(size_t)(r0 + 2*p + 1)*HD + j] = fmaxf(acc[p].y, 0.f);
    }
}

// ---------------- fc2: preds = q @ fc2_w^T + b. grid (250 n-tiles, 4 row-groups) ----------
__global__ void k_fc2(const float* __restrict__ fc2b, float* __restrict__ preds) {
    __shared__ float xs[HD][16];      // [k][row] 16KB
    int tid = threadIdx.x;
    int n = blockIdx.x*128 + tid;
    int rg = blockIdx.y;
    float bn = fc2b[n];
    for (int chunk = 0; chunk < 32; chunk++) {
        int rbase = rg*512 + chunk*16;
        __syncthreads();
        for (int idx = tid; idx < 16*HD; idx += 128) {
            int r = idx >> 8, k = idx & 255;
            xs[k][r] = g_q[(size_t)(rbase + r)*HD + k];
        }
        __syncthreads();
        float2 acc[8];
        #pragma unroll
        for (int p = 0; p < 8; p++) acc[p] = make_float2(0.f, 0.f);
        #pragma unroll 2
        for (int k = 0; k < HD; k++) {
            float w = g_fc2wT[(size_t)k*VOCAB + n];
            float2 wp = make_float2(w, w);
            float4 x0 = *(const float4*)&xs[k][0];
            float4 x1 = *(const float4*)&xs[k][4];
            float4 x2 = *(const float4*)&xs[k][8];
            float4 x3 = *(const float4*)&xs[k][12];
            acc[0] = ffma2(wp, make_float2(x0.x, x0.y), acc[0]);
            acc[1] = ffma2(wp, make_float2(x0.z, x0.w), acc[1]);
            acc[2] = ffma2(wp, make_float2(x1.x, x1.y), acc[2]);
            acc[3] = ffma2(wp, make_float2(x1.z, x1.w), acc[3]);
            acc[4] = ffma2(wp, make_float2(x2.x, x2.y), acc[4]);
            acc[5] = ffma2(wp, make_float2(x2.z, x2.w), acc[5]);
            acc[6] = ffma2(wp, make_float2(x3.x, x3.y), acc[6]);
            acc[7] = ffma2(wp, make_float2(x3.z, x3.w), acc[7]);
        }
        #pragma unroll
        for (int p = 0; p < 8; p++) {
            preds[(size_t)(rbase + 2*p)*VOCAB + n]     = acc[p].x + bn;
            preds[(size_t)(rbase + 2*p + 1)*VOCAB + n] = acc[p].y + bn;
        }
    }
}

// ---------------- loss: per-row log-softmax nll (2-pass), then reduce ----------------
__global__ void k_loss(const float* __restrict__ preds, const int* __restrict__ yout) {
    __shared__ float rsh[8];
    __shared__ float s_mx, s_sum;
    int row = blockIdx.x, tid = threadIdx.x;
    const float* p = preds + (size_t)row*VOCAB;
    float m = -1e30f;
    for (int v = tid; v < VOCAB; v += 256) m = fmaxf(m, p[v]);
    #pragma unroll
    for (int o = 16; o; o >>= 1) m = fmaxf(m, __shfl_xor_sync(0xffffffffu, m, o));
    if ((tid & 31) == 0) rsh[tid >> 5] = m;
    __syncthreads();
    if (tid == 0) {
        float v = rsh[0];
        for (int w = 1; w < 8; w++) v = fmaxf(v, rsh[w]);
        s_mx = v;
    }
    __syncthreads();
    float mx = s_mx;
    float s = 0.f;
    for (int v = tid; v < VOCAB; v += 256) s += __expf(p[v] - mx);
    #pragma unroll
    for (int o = 16; o; o >>= 1) s += __shfl_xor_sync(0xffffffffu, s, o);
    if ((tid & 31) == 0) rsh[tid >> 5] = s;
    __syncthreads();
    if (tid == 0) {
        float v = 0.f;
        for (int w = 0; w < 8; w++) v += rsh[w];
        s_sum = v;
    }
    __syncthreads();
    if (tid == 0) {
        int tgt = yout[row];
        float xt = p[tgt];
        float nll = mx + logf(s_sum) - xt;
        float msk = (tgt != 0) ? 1.f : 0.f;
        g_nll[row] = nll * msk;
        g_msk[row] = msk;
    }
}

__global__ void k_loss_final(float* __restrict__ out, int out_idx) {
    __shared__ float ra[8], rb[8];
    int tid = threadIdx.x;
    float a = 0.f, b = 0.f;
    for (int r = tid; r < ROWS_TOT; r += 256) { a += g_nll[r]; b += g_msk[r]; }
    #pragma unroll
    for (int o = 16; o; o >>= 1) {
        a += __shfl_xor_sync(0xffffffffu, a, o);
        b += __shfl_xor_sync(0xffffffffu, b, o);
    }
    if ((tid & 31) == 0) { ra[tid >> 5] = a; rb[tid >> 5] = b; }
    __syncthreads();
    if (tid == 0) {
        float sa = 0.f, sb = 0.f;
        for (int w = 0; w < 8; w++) { sa += ra[w]; sb += rb[w]; }
        out[out_idx] = sa / fmaxf(sb, 1.f);
    }
}

// ---------------- launch ----------------
extern "C" void kernel_launch(void* const* d_in, const int* in_sizes, int n_in,
                              void* d_out, int out_size) {
    const int*   y_in   = (const int*)  d_in[0];
    const int*   y_out  = (const int*)  d_in[1];
    const float* y_enc  = (const float*)d_in[2];
    // d_in[3] = h_enc (unused: reference zeroes it)
    const float* emb    = (const float*)d_in[4];
    const float* f1_w1  = (const float*)d_in[5];
    const float* f1_b1  = (const float*)d_in[6];
    const float* f1_w2  = (const float*)d_in[7];
    const float* f1_b2  = (const float*)d_in[8];
    const float* f2_w1  = (const float*)d_in[9];
    const float* f2_b1  = (const float*)d_in[10];
    const float* f2_w2  = (const float*)d_in[11];
    const float* f2_b2  = (const float*)d_in[12];
    const float* g_wih  = (const float*)d_in[13];
    const float* g_bih  = (const float*)d_in[14];
    const float* g_whh  = (const float*)d_in[15];
    const float* g_bhh  = (const float*)d_in[16];
    const float* fc1_w  = (const float*)d_in[17];
    const float* fc1_b  = (const float*)d_in[18];
    const float* fc2_w  = (const float*)d_in[19];
    const float* fc2_b  = (const float*)d_in[20];

    float* preds = (float*)d_out;
    const long long TBV = (long long)TS*BB*VOCAB;

    k_zero<<<(2*HD*BB + 255)/256, 256>>>();

    dim3 tb(32, 8);
    k_transpose<<<dim3(8,   8), tb>>>(f1_w1, 0, HD,    HD);
    k_transpose<<<dim3(8,   2), tb>>>(f1_w2, 1, AD,    HD);
    k_transpose<<<dim3(8,   8), tb>>>(f2_w1, 2, HD,    HD);
    k_transpose<<<dim3(8,   2), tb>>>(f2_w2, 3, AD,    HD);
    k_transpose<<<dim3(16,  8), tb>>>(fc1_w, 4, HD,    H2);
    k_transpose<<<dim3(8, 1000), tb>>>(fc2_w, 5, VOCAB, HD);

    k_embT<<<TS, HD>>>(y_in, emb);
    k_c2<<<(SQ*BB)/16, 256>>>(y_enc, f2_b1, f2_b2);

    for (int t = 0; t < TS; t++) {
        k_gru<<<HD/2, 256>>>(t, g_wih, g_bih, g_whh, g_bhh);
        k_attn<<<BB, 256>>>(t, f1_b1, f1_b2);
        k_ctx<<<dim3(BB, HD/32), 128>>>(t, y_enc);
    }

    k_fc1<<<ROWS_TOT/16, 256>>>(fc1_b);
    k_fc2<<<dim3(VOCAB/128, 4), 128>>>(fc2_b, preds);

    if ((long long)out_size >= TBV + 1) {
        k_loss<<<ROWS_TOT, 256>>>(preds, y_out);
        k_loss_final<<<1, 256>>>(preds, (int)TBV);
    }
}

// round 6
// speedup vs baseline: 1.0005x; 1.0005x over previous
#include <cuda_runtime.h>
#include <cuda_bf16.h>
#include <math.h>

#define HD      256
#define AD      64
#define VOCAB   32000
#define TS      64
#define BB      32
#define SQ      1024
#define H2      512
#define ROWS_TOT (TS*BB)   /* 2048 */

// ---------------- scratch: static device globals (no allocation) ----------------
__device__ float g_embT[TS*HD*BB];                 // [t][i][b]
__device__ float g_hT[2*HD*BB];                    // ping-pong [p][k][b]
__device__ float g_ctxT[2*HD*BB];                  // ping-pong [p][h][b]
__device__ float g_c2[(size_t)BB*AD*SQ];           // [b][a][s]
__device__ float g_attw[BB*SQ];                    // [b][s]
__device__ float g_obuf[(size_t)ROWS_TOT*H2];      // [t*B+b][0:256 h | 256:512 ctx]
__device__ float g_q[(size_t)ROWS_TOT*HD];         // fc1 output
__device__ float g_f1w1T[HD*HD];
__device__ float g_f1w2T[HD*AD];
__device__ float g_f2w1T[HD*HD];
__device__ float g_f2w2T[HD*AD];
__device__ float g_fc1wT[H2*HD];
__device__ float g_fc2wT[(size_t)HD*VOCAB];        // [k][n]
__device__ float g_nll[ROWS_TOT];
__device__ float g_msk[ROWS_TOT];

// packed f32x2 fma (sm_103a)
__device__ __forceinline__ float2 ffma2(float2 a, float2 b, float2 c) {
    union U { float2 f; unsigned long long u; };
    U ua, ub, uc, ud;
    ua.f = a; ub.f = b; uc.f = c;
    asm("fma.rn.f32x2 %0, %1, %2, %3;" : "=l"(ud.u) : "l"(ua.u), "l"(ub.u), "l"(uc.u));
    return ud.f;
}

// ---------------- prep ----------------
__global__ void k_zero() {
    int i = blockIdx.x * blockDim.x + threadIdx.x;
    if (i < 2*HD*BB) { g_hT[i] = 0.f; g_ctxT[i] = 0.f; }
}

// dst[c*rows + r] = src[r*cols + c]
__global__ void k_transpose(const float* __restrict__ src, int dst_id, int rows, int cols) {
    float* dst = (dst_id == 0) ? g_f1w1T : (dst_id == 1) ? g_f1w2T :
                 (dst_id == 2) ? g_f2w1T : (dst_id == 3) ? g_f2w2T :
                 (dst_id == 4) ? g_fc1wT : g_fc2wT;
    __shared__ float tile[32][33];
    int c0 = blockIdx.x * 32, r0 = blockIdx.y * 32;
    int tx = threadIdx.x, ty = threadIdx.y;
    for (int j = ty; j < 32; j += 8) {
        int r = r0 + j, c = c0 + tx;
        if (r < rows && c < cols) tile[j][tx] = src[(size_t)r*cols + c];
    }
    __syncthreads();
    for (int j = ty; j < 32; j += 8) {
        int r = r0 + tx, c = c0 + j;
        if (r < rows && c < cols) dst[(size_t)c*rows + r] = tile[tx][j];
    }
}

__global__ void k_embT(const int* __restrict__ yin, const float* __restrict__ emb) {
    int t = blockIdx.x, i = threadIdx.x;
    for (int b = 0; b < BB; b++) {
        int row = yin[t*BB + b];
        g_embT[((size_t)t*HD + i)*BB + b] = emb[(size_t)row*HD + i];
    }
}

// ---------------- c2 = tanh(relu(y_enc @ f2w1^T + b1) @ f2w2^T + b2), stored [b][a][s] ----
__global__ void k_c2(const float* __restrict__ yenc,
                     const float* __restrict__ b1, const float* __restrict__ b2) {
    __shared__ float2 ysp[HD][8];     // [i][row-pair]  16KB
    __shared__ float  hid[16][HD];    // 16KB
    int r0 = blockIdx.x * 16;
    int tid = threadIdx.x;
    float* ysf = (float*)ysp;         // viewed as [i][16] floats
    for (int idx = tid; idx < 16*HD; idx += 256) {
        int r = idx >> 8, i = idx & 255;
        ysf[i*16 + r] = yenc[(size_t)(r0 + r)*HD + i];
    }
    __syncthreads();
    {   // layer 1: thread j computes 16 rows
        int j = tid;
        float bj = b1[j];
        float2 acc[8];
        #pragma unroll
        for (int p = 0; p < 8; p++) acc[p] = make_float2(bj, bj);
        for (int i = 0; i < HD; i++) {
            float w = g_f2w1T[i*HD + j];
            float2 wp = make_float2(w, w);
            #pragma unroll
            for (int p = 0; p < 8; p++) acc[p] = ffma2(wp, ysp[i][p], acc[p]);
        }
        #pragma unroll
        for (int p = 0; p < 8; p++) {
            hid[2*p][j]   = fmaxf(acc[p].x, 0.f);
            hid[2*p+1][j] = fmaxf(acc[p].y, 0.f);
        }
    }
    __syncthreads();
    #pragma unroll
    for (int q = 0; q < 4; q++) {
        int o = tid + q*256;              // 16 rows x 64 a
        int rr = o >> 6, a = o & 63;
        float acc = b2[a];
        for (int i = 0; i < HD; i++) acc = fmaf(hid[rr][i], g_f2w2T[i*AD + a], acc);
        int gr = r0 + rr;                 // gr = s*32 + b
        int s = gr >> 5, b = gr & 31;
        g_c2[((size_t)b*AD + a)*SQ + s] = tanhf(acc);
    }
}

// ---------------- GRU step: 128 blocks x 256 threads, 2 k's per block ----------------
__global__ void k_gru(int t,
                      const float* __restrict__ wih, const float* __restrict__ bih,
                      const float* __restrict__ whh, const float* __restrict__ bhh) {
    __shared__ float red[2][4][6][32];
    int tid = threadIdx.x;
    int lane = tid & 31, seg = (tid >> 5) & 3, kk = tid >> 7;
    int k = blockIdx.x*2 + kk;
    const float* embt = g_embT + (size_t)t*HD*BB;
    const float* ctxt = g_ctxT + (size_t)(t & 1)*HD*BB;
    const float* ht   = g_hT   + (size_t)(t & 1)*HD*BB;
    const float* wr = wih + (size_t)k*H2;
    const float* wz = wih + (size_t)(HD + k)*H2;
    const float* wn = wih + (size_t)(2*HD + k)*H2;
    float a_r = 0.f, a_z = 0.f, a_n = 0.f;
    int ibase = seg*128;
    const float* xp = (seg < 2) ? (embt + (size_t)ibase*BB + lane)
                                : (ctxt + (size_t)(ibase - 256)*BB + lane);
    #pragma unroll 4
    for (int ii = 0; ii < 128; ii++) {
        float x = xp[(size_t)ii*BB];
        int i = ibase + ii;
        a_r = fmaf(wr[i], x, a_r);
        a_z = fmaf(wz[i], x, a_z);
        a_n = fmaf(wn[i], x, a_n);
    }
    const float* vr = whh + (size_t)k*HD;
    const float* vz = whh + (size_t)(HD + k)*HD;
    const float* vn = whh + (size_t)(2*HD + k)*HD;
    float b_r = 0.f, b_z = 0.f, b_n = 0.f;
    int jbase = seg*64;
    const float* hp = ht + (size_t)jbase*BB + lane;
    #pragma unroll 4
    for (int ii = 0; ii < 64; ii++) {
        float hv = hp[(size_t)ii*BB];
        int i = jbase + ii;
        b_r = fmaf(vr[i], hv, b_r);
        b_z = fmaf(vz[i], hv, b_z);
        b_n = fmaf(vn[i], hv, b_n);
    }
    red[kk][seg][0][lane] = a_r; red[kk][seg][1][lane] = a_z; red[kk][seg][2][lane] = a_n;
    red[kk][seg][3][lane] = b_r; red[kk][seg][4][lane] = b_z; red[kk][seg][5][lane] = b_n;
    __syncthreads();
    if (tid < 64) {
        int kk2 = tid >> 5, ln = tid & 31;
        int k2 = blockIdx.x*2 + kk2;
        float s[6];
        #pragma unroll
        for (int g = 0; g < 6; g++)
            s[g] = red[kk2][0][g][ln] + red[kk2][1][g][ln] + red[kk2][2][g][ln] + red[kk2][3][g][ln];
        float gr_ = s[0] + bih[k2]      + s[3] + bhh[k2];
        float gz_ = s[1] + bih[HD + k2] + s[4] + bhh[HD + k2];
        float r = 1.f / (1.f + expf(-gr_));
        float z = 1.f / (1.f + expf(-gz_));
        float n = tanhf((s[2] + bih[2*HD + k2]) + r*(s[5] + bhh[2*HD + k2]));
        float hprev = g_hT[(size_t)(t & 1)*HD*BB + (size_t)k2*BB + ln];
        float hn = (1.f - z)*n + z*hprev;
        g_hT[(size_t)((t + 1) & 1)*HD*BB + (size_t)k2*BB + ln] = hn;
        g_obuf[(size_t)(t*BB + ln)*H2 + k2] = hn;
    }
}

// ---------------- attention: c1 + scores + softmax (one block per batch) ----------------
__global__ void k_attn(int t, const float* __restrict__ f1b1, const float* __restrict__ f1b2) {
    __shared__ float hsm[HD];
    __shared__ float hid[HD];
    __shared__ float c1s[AD];
    __shared__ float rsh[8];
    __shared__ float s_mx, s_sum;
    int b = blockIdx.x, tid = threadIdx.x;
    const float* hT = g_hT + (size_t)((t + 1) & 1)*HD*BB;
    hsm[tid] = hT[(size_t)tid*BB + b];
    __syncthreads();
    {   // hidden = relu(f1w1 @ h + b1)
        float acc = f1b1[tid];
        for (int i = 0; i < HD; i++) acc = fmaf(g_f1w1T[i*HD + tid], hsm[i], acc);
        hid[tid] = fmaxf(acc, 0.f);
    }
    __syncthreads();
    if (tid < AD) {
        float acc = f1b2[tid];
        for (int i = 0; i < HD; i++) acc = fmaf(g_f1w2T[i*AD + tid], hid[i], acc);
        c1s[tid] = tanhf(acc);
    }
    __syncthreads();
    // scores: 4 s-values per thread
    const float* c2b = g_c2 + (size_t)b*AD*SQ;
    float sc[4];
    float mloc = -1e30f;
    #pragma unroll
    for (int q = 0; q < 4; q++) {
        int s = tid + q*256;
        float acc = 0.f;
        #pragma unroll 4
        for (int a = 0; a < AD; a++) acc = fmaf(c1s[a], c2b[(size_t)a*SQ + s], acc);
        sc[q] = acc;
        mloc = fmaxf(mloc, acc);
    }
    // block max
    #pragma unroll
    for (int o = 16; o; o >>= 1) mloc = fmaxf(mloc, __shfl_xor_sync(0xffffffffu, mloc, o));
    if ((tid & 31) == 0) rsh[tid >> 5] = mloc;
    __syncthreads();
    if (tid == 0) {
        float v = rsh[0];
        for (int w = 1; w < 8; w++) v = fmaxf(v, rsh[w]);
        s_mx = v;
    }
    __syncthreads();
    float mx = s_mx;
    float sloc = 0.f;
    #pragma unroll
    for (int q = 0; q < 4; q++) { sc[q] = __expf(sc[q] - mx); sloc += sc[q]; }
    #pragma unroll
    for (int o = 16; o; o >>= 1) sloc += __shfl_xor_sync(0xffffffffu, sloc, o);
    if ((tid & 31) == 0) rsh[tid >> 5] = sloc;
    __syncthreads();
    if (tid == 0) {
        float v = 0.f;
        for (int w = 0; w < 8; w++) v += rsh[w];
        s_sum = v;
    }
    __syncthreads();
    float inv = 1.f / s_sum;
    #pragma unroll
    for (int q = 0; q < 4; q++) g_attw[b*SQ + tid + q*256] = sc[q] * inv;
}

// ---------------- ctx = attw @ y_enc : grid (32 b, 8 h-chunks), 128 threads ----------------
__global__ void k_ctx(int t, const float* __restrict__ yenc) {
    __shared__ float red[4][32];
    int b = blockIdx.x, hc = blockIdx.y;
    int tid = threadIdx.x, wi = tid >> 5, lane = tid & 31;
    int h = hc*32 + lane;
    const float* aw = g_attw + b*SQ;
    float acc = 0.f;
    int s0 = wi*256;
    #pragma unroll 4
    for (int ii = 0; ii < 256; ii++) {
        int s = s0 + ii;
        acc = fmaf(aw[s], yenc[((size_t)s*BB + b)*HD + h], acc);
    }
    red[wi][lane] = acc;
    __syncthreads();
    if (tid < 32) {
        int hh = hc*32 + tid;
        float v = red[0][tid] + red[1][tid] + red[2][tid] + red[3][tid];
        g_ctxT[(size_t)((t + 1) & 1)*HD*BB + (size_t)hh*BB + b] = v;
        g_obuf[(size_t)(t*BB + b)*H2 + HD + hh] = v;
    }
}

// ---------------- fc1: q = relu(obuf @ fc1_w^T + b), 16 rows/block ----------------
__global__ void k_fc1(const float* __restrict__ fc1b) {
    __shared__ float2 xsp[H2][8];     // 32KB
    int r0 = blockIdx.x * 16;
    int tid = threadIdx.x;
    float* xsf = (float*)xsp;
    for (int idx = tid; idx < 16*H2; idx += 256) {
        int r = idx >> 9, i = idx & 511;
        xsf[i*16 + r] = g_obuf[(size_t)(r0 + r)*H2 + i];
    }
    __syncthreads();
    int j = tid;
    float bj = fc1b[j];
    float2 acc[8];
    #pragma unroll
    for (int p = 0; p < 8; p++) acc[p] = make_float2(bj, bj);
    for (int i = 0; i < H2; i++) {
        float w = g_fc1wT[i*HD + j];
        float2 wp = make_float2(w, w);
        #pragma unroll
        for (int p = 0; p < 8; p++) acc[p] = ffma2(wp, xsp[i][p], acc[p]);
    }
    #pragma unroll
    for (int p = 0; p < 8; p++) {
        g_q[(size_t)(r0 + 2*p)*HD + j]     = fmaxf(acc[p].x, 0.f);
        g_q[(size_t)(r0 + 2*p + 1)*HD + j] = fmaxf(acc[p].y, 0.f);
    }
}

// ---------------- fc2: preds = q @ fc2_w^T + b. grid (250 n-tiles, 4 row-groups) ----------
__global__ void k_fc2(const float* __restrict__ fc2b, float* __restrict__ preds) {
    __shared__ float xs[HD][16];      // [k][row] 16KB
    int tid = threadIdx.x;
    int n = blockIdx.x*128 + tid;
    int rg = blockIdx.y;
    float bn = fc2b[n];
    for (int chunk = 0; chunk < 32; chunk++) {
        int rbase = rg*512 + chunk*16;
        __syncthreads();
        for (int idx = tid; idx < 16*HD; idx += 128) {
            int r = idx >> 8, k = idx & 255;
            xs[k][r] = g_q[(size_t)(rbase + r)*HD + k];
        }
        __syncthreads();
        float2 acc[8];
        #pragma unroll
        for (int p = 0; p < 8; p++) acc[p] = make_float2(0.f, 0.f);
        #pragma unroll 2
        for (int k = 0; k < HD; k++) {
            float w = g_fc2wT[(size_t)k*VOCAB + n];
            float2 wp = make_float2(w, w);
            float4 x0 = *(const float4*)&xs[k][0];
            float4 x1 = *(const float4*)&xs[k][4];
            float4 x2 = *(const float4*)&xs[k][8];
            float4 x3 = *(const float4*)&xs[k][12];
            acc[0] = ffma2(wp, make_float2(x0.x, x0.y), acc[0]);
            acc[1] = ffma2(wp, make_float2(x0.z, x0.w), acc[1]);
            acc[2] = ffma2(wp, make_float2(x1.x, x1.y), acc[2]);
            acc[3] = ffma2(wp, make_float2(x1.z, x1.w), acc[3]);
            acc[4] = ffma2(wp, make_float2(x2.x, x2.y), acc[4]);
            acc[5] = ffma2(wp, make_float2(x2.z, x2.w), acc[5]);
            acc[6] = ffma2(wp, make_float2(x3.x, x3.y), acc[6]);
            acc[7] = ffma2(wp, make_float2(x3.z, x3.w), acc[7]);
        }
        #pragma unroll
        for (int p = 0; p < 8; p++) {
            preds[(size_t)(rbase + 2*p)*VOCAB + n]     = acc[p].x + bn;
            preds[(size_t)(rbase + 2*p + 1)*VOCAB + n] = acc[p].y + bn;
        }
    }
}

// ---------------- loss: per-row log-softmax nll (2-pass), then reduce ----------------
__global__ void k_loss(const float* __restrict__ preds, const int* __restrict__ yout) {
    __shared__ float rsh[8];
    __shared__ float s_mx, s_sum;
    int row = blockIdx.x, tid = threadIdx.x;
    const float* p = preds + (size_t)row*VOCAB;
    float m = -1e30f;
    for (int v = tid; v < VOCAB; v += 256) m = fmaxf(m, p[v]);
    #pragma unroll
    for (int o = 16; o; o >>= 1) m = fmaxf(m, __shfl_xor_sync(0xffffffffu, m, o));
    if ((tid & 31) == 0) rsh[tid >> 5] = m;
    __syncthreads();
    if (tid == 0) {
        float v = rsh[0];
        for (int w = 1; w < 8; w++) v = fmaxf(v, rsh[w]);
        s_mx = v;
    }
    __syncthreads();
    float mx = s_mx;
    float s = 0.f;
    for (int v = tid; v < VOCAB; v += 256) s += __expf(p[v] - mx);
    #pragma unroll
    for (int o = 16; o; o >>= 1) s += __shfl_xor_sync(0xffffffffu, s, o);
    if ((tid & 31) == 0) rsh[tid >> 5] = s;
    __syncthreads();
    if (tid == 0) {
        float v = 0.f;
        for (int w = 0; w < 8; w++) v += rsh[w];
        s_sum = v;
    }
    __syncthreads();
    if (tid == 0) {
        int tgt = yout[row];
        float xt = p[tgt];
        float nll = mx + logf(s_sum) - xt;
        float msk = (tgt != 0) ? 1.f : 0.f;
        g_nll[row] = nll * msk;
        g_msk[row] = msk;
    }
}

__global__ void k_loss_final(float* __restrict__ out, int out_idx) {
    __shared__ float ra[8], rb[8];
    int tid = threadIdx.x;
    float a = 0.f, b = 0.f;
    for (int r = tid; r < ROWS_TOT; r += 256) { a += g_nll[r]; b += g_msk[r]; }
    #pragma unroll
    for (int o = 16; o; o >>= 1) {
        a += __shfl_xor_sync(0xffffffffu, a, o);
        b += __shfl_xor_sync(0xffffffffu, b, o);
    }
    if ((tid & 31) == 0) { ra[tid >> 5] = a; rb[tid >> 5] = b; }
    __syncthreads();
    if (tid == 0) {
        float sa = 0.f, sb = 0.f;
        for (int w = 0; w < 8; w++) { sa += ra[w]; sb += rb[w]; }
        out[out_idx] = sa / fmaxf(sb, 1.f);
    }
}

// ---------------- launch ----------------
extern "C" void kernel_launch(void* const* d_in, const int* in_sizes, int n_in,
                              void* d_out, int out_size) {
    const int*   y_in   = (const int*)  d_in[0];
    const int*   y_out  = (const int*)  d_in[1];
    const float* y_enc  = (const float*)d_in[2];
    // d_in[3] = h_enc (unused: reference zeroes it)
    const float* emb    = (const float*)d_in[4];
    const float* f1_w1  = (const float*)d_in[5];
    const float* f1_b1  = (const float*)d_in[6];
    const float* f1_w2  = (const float*)d_in[7];
    const float* f1_b2  = (const float*)d_in[8];
    const float* f2_w1  = (const float*)d_in[9];
    const float* f2_b1  = (const float*)d_in[10];
    const float* f2_w2  = (const float*)d_in[11];
    const float* f2_b2  = (const float*)d_in[12];
    const float* g_wih  = (const float*)d_in[13];
    const float* g_bih  = (const float*)d_in[14];
    const float* g_whh  = (const float*)d_in[15];
    const float* g_bhh  = (const float*)d_in[16];
    const float* fc1_w  = (const float*)d_in[17];
    const float* fc1_b  = (const float*)d_in[18];
    const float* fc2_w  = (const float*)d_in[19];
    const float* fc2_b  = (const float*)d_in[20];

    float* preds = (float*)d_out;
    const long long TBV = (long long)TS*BB*VOCAB;

    k_zero<<<(2*HD*BB + 255)/256, 256>>>();

    dim3 tb(32, 8);
    k_transpose<<<dim3(8,   8), tb>>>(f1_w1, 0, HD,    HD);
    k_transpose<<<dim3(8,   2), tb>>>(f1_w2, 1, AD,    HD);
    k_transpose<<<dim3(8,   8), tb>>>(f2_w1, 2, HD,    HD);
    k_transpose<<<dim3(8,   2), tb>>>(f2_w2, 3, AD,    HD);
    k_transpose<<<dim3(16,  8), tb>>>(fc1_w, 4, HD,    H2);
    k_transpose<<<dim3(8, 1000), tb>>>(fc2_w, 5, VOCAB, HD);

    k_embT<<<TS, HD>>>(y_in, emb);
    k_c2<<<(SQ*BB)/16, 256>>>(y_enc, f2_b1, f2_b2);

    for (int t = 0; t < TS; t++) {
        k_gru<<<HD/2, 256>>>(t, g_wih, g_bih, g_whh, g_bhh);
        k_attn<<<BB, 256>>>(t, f1_b1, f1_b2);
        k_ctx<<<dim3(BB, HD/32), 128>>>(t, y_enc);
    }

    k_fc1<<<ROWS_TOT/16, 256>>>(fc1_b);
    k_fc2<<<dim3(VOCAB/128, 4), 128>>>(fc2_b, preds);

    if ((long long)out_size >= TBV + 1) {
        k_loss<<<ROWS_TOT, 256>>>(preds, y_out);
        k_loss_final<<<1, 256>>>(preds, (int)TBV);
    }
}

// round 7
// speedup vs baseline: 1.2320x; 1.2314x over previous
#include <cuda_runtime.h>
#include <math.h>

#define HD 256
#define AD 64
#define VOCAB 32000
#define TS 64
#define BB 32
#define SQ 1024
#define H2 512
#define ROWS_TOT (TS*BB)
#define NB 32

__device__ float g_embT[TS*HD*BB];             // [t][i][b]
__device__ float g_hT[2*HD*BB];                // ping-pong [p][k][b]
__device__ float g_ctxT[2*HD*BB];              // ping-pong [p][h][b]
__device__ float g_hid[HD*BB];                 // [j][b]
__device__ float g_c2[(size_t)BB*AD*SQ];       // [b][a][s]
__device__ float g_obuf[(size_t)ROWS_TOT*H2];
__device__ float g_q[(size_t)ROWS_TOT*HD];
__device__ float g_f1w2T[HD*AD];
__device__ float g_f2w1T[HD*HD];
__device__ float g_f2w2T[HD*AD];
__device__ float g_fc1wT[H2*HD];
__device__ float g_fc2wT[(size_t)HD*VOCAB];
__device__ float g_nll[ROWS_TOT];
__device__ float g_msk[ROWS_TOT];
__device__ unsigned g_bar;

__device__ __forceinline__ float2 ffma2(float2 a, float2 b, float2 c) {
    union U { float2 f; unsigned long long u; };
    U ua, ub, uc, ud; ua.f = a; ub.f = b; uc.f = c;
    asm("fma.rn.f32x2 %0, %1, %2, %3;" : "=l"(ud.u) : "l"(ua.u), "l"(ub.u), "l"(uc.u));
    return ud.f;
}
__device__ __forceinline__ float2 b2f(float w) { return make_float2(w, w); }
__device__ __forceinline__ float2 add2(float2 a, float2 b) { return make_float2(a.x+b.x, a.y+b.y); }

__global__ void k_zero() {
    int i = blockIdx.x*blockDim.x + threadIdx.x;
    if (i < 2*HD*BB) { g_hT[i] = 0.f; g_ctxT[i] = 0.f; }
    if (i == 0) g_bar = 0u;
}

__global__ void k_transpose(const float* __restrict__ src, int id, int rows, int cols) {
    float* dst = (id==0)?g_f2w1T:(id==1)?g_f2w2T:(id==2)?g_fc1wT:(id==3)?g_f1w2T:g_fc2wT;
    __shared__ float tile[32][33];
    int c0 = blockIdx.x*32, r0 = blockIdx.y*32, tx = threadIdx.x, ty = threadIdx.y;
    for (int j = ty; j < 32; j += 8) {
        int r = r0+j, c = c0+tx;
        if (r < rows && c < cols) tile[j][tx] = src[(size_t)r*cols + c];
    }
    __syncthreads();
    for (int j = ty; j < 32; j += 8) {
        int r = r0+tx, c = c0+j;
        if (r < rows && c < cols) dst[(size_t)c*rows + r] = tile[tx][j];
    }
}

__global__ void k_embT(const int* __restrict__ yin, const float* __restrict__ emb) {
    int t = blockIdx.x, i = threadIdx.x;
    for (int b = 0; b < BB; b++)
        g_embT[((size_t)t*HD + i)*BB + b] = emb[(size_t)yin[t*BB+b]*HD + i];
}

// c2 stored [b][a][s]
__global__ void k_c2(const float* __restrict__ yenc,
                     const float* __restrict__ b1, const float* __restrict__ b2) {
    __shared__ float2 ysp[HD][8];
    __shared__ float  hid[16][HD];
    int r0 = blockIdx.x*16, tid = threadIdx.x;
    float* ysf = (float*)ysp;
    for (int idx = tid; idx < 16*HD; idx += 256) {
        int r = idx >> 8, i = idx & 255;
        ysf[i*16 + r] = yenc[(size_t)(r0+r)*HD + i];
    }
    __syncthreads();
    {
        int j = tid; float bj = b1[j];
        float2 acc[8];
        #pragma unroll
        for (int p = 0; p < 8; p++) acc[p] = make_float2(bj, bj);
        for (int i = 0; i < HD; i++) {
            float2 wp = b2f(g_f2w1T[i*HD + j]);
            #pragma unroll
            for (int p = 0; p < 8; p++) acc[p] = ffma2(wp, ysp[i][p], acc[p]);
        }
        #pragma unroll
        for (int p = 0; p < 8; p++) {
            hid[2*p][j]   = fmaxf(acc[p].x, 0.f);
            hid[2*p+1][j] = fmaxf(acc[p].y, 0.f);
        }
    }
    __syncthreads();
    #pragma unroll
    for (int q = 0; q < 4; q++) {
        int o = tid + q*256, rr = o >> 6, a = o & 63;
        float acc = b2[a];
        for (int i = 0; i < HD; i++) acc = fmaf(hid[rr][i], g_f2w2T[i*AD + a], acc);
        int gr = r0 + rr, s = gr >> 5, b = gr & 31;
        g_c2[((size_t)b*AD + a)*SQ + s] = tanhf(acc);
    }
}

// -------- persistent decode loop: 32 blocks x 256 threads --------
__global__ void __launch_bounds__(256, 1)
k_loop(const float* __restrict__ yenc,
       const float* __restrict__ wih, const float* __restrict__ bih,
       const float* __restrict__ whh, const float* __restrict__ bhh,
       const float* __restrict__ f1w1, const float* __restrict__ f1b1,
       const float* __restrict__ f1b2) {
    extern __shared__ float sdyn[];          // 64KB: [0:8192) h/hn, [8192:16384) ctx
    float2* s_h = (float2*)sdyn;             // [k][bp]
    float2* s_c = (float2*)(sdyn + 8192);    // [h][bp]
    __shared__ float2 red[2][8][16][4];
    __shared__ float s_hid[HD];
    __shared__ float c1s[AD];
    __shared__ float attw[SQ];
    __shared__ float2 cred[4][64][2];
    __shared__ float rsh[8];
    __shared__ float sh_mx, sh_sum;

    int g = blockIdx.x, tid = threadIdx.x;
    int p = tid >> 7, kl = (tid >> 4) & 7, bp = tid & 15;
    int k = g*8 + kl;
    unsigned bar = 0;
    const float* wr = wih + (size_t)k*H2;
    const float* wz = wih + (size_t)(HD + k)*H2;
    const float* wn = wih + (size_t)(2*HD + k)*H2;
    const float* vr = whh + (size_t)k*HD;
    const float* vz = whh + (size_t)(HD + k)*HD;
    const float* vn = whh + (size_t)(2*HD + k)*HD;
    const float2 z2 = make_float2(0.f, 0.f);

    for (int t = 0; t < TS; t++) {
        int cur = t & 1, nxt = cur ^ 1;
        // stage h(cur), ctx(cur) into smem (L2-coherent loads)
        {
            const float4* hs = (const float4*)(g_hT + (size_t)cur*HD*BB);
            const float4* cs = (const float4*)(g_ctxT + (size_t)cur*HD*BB);
            float4* d0 = (float4*)s_h; float4* d1 = (float4*)s_c;
            for (int i = tid; i < 2048; i += 256) { d0[i] = __ldcg(hs + i); d1[i] = __ldcg(cs + i); }
        }
        __syncthreads();
        // ---- phase G: GRU ----
        {
            const float2* xe = (const float2*)(g_embT + (size_t)t*HD*BB);
            float2 ar = z2, az = ar, an1 = ar, an2 = ar;
            if (p == 0) {
                #pragma unroll 2
                for (int j = 0; j < 256; j += 4) {
                    float4 fr = *(const float4*)(wr+j), fz = *(const float4*)(wz+j), fn = *(const float4*)(wn+j);
                    float2 x0 = xe[(j+0)*16+bp], x1 = xe[(j+1)*16+bp], x2 = xe[(j+2)*16+bp], x3 = xe[(j+3)*16+bp];
                    ar = ffma2(b2f(fr.x),x0,ar); ar = ffma2(b2f(fr.y),x1,ar); ar = ffma2(b2f(fr.z),x2,ar); ar = ffma2(b2f(fr.w),x3,ar);
                    az = ffma2(b2f(fz.x),x0,az); az = ffma2(b2f(fz.y),x1,az); az = ffma2(b2f(fz.z),x2,az); az = ffma2(b2f(fz.w),x3,az);
                    an1= ffma2(b2f(fn.x),x0,an1);an1= ffma2(b2f(fn.y),x1,an1);an1= ffma2(b2f(fn.z),x2,an1);an1= ffma2(b2f(fn.w),x3,an1);
                }
                #pragma unroll 2
                for (int j = 256; j < 384; j += 4) {
                    float4 fr = *(const float4*)(wr+j), fz = *(const float4*)(wz+j), fn = *(const float4*)(wn+j);
                    float2 x0 = s_c[(j-256)*16+bp], x1 = s_c[(j-255)*16+bp], x2 = s_c[(j-254)*16+bp], x3 = s_c[(j-253)*16+bp];
                    ar = ffma2(b2f(fr.x),x0,ar); ar = ffma2(b2f(fr.y),x1,ar); ar = ffma2(b2f(fr.z),x2,ar); ar = ffma2(b2f(fr.w),x3,ar);
                    az = ffma2(b2f(fz.x),x0,az); az = ffma2(b2f(fz.y),x1,az); az = ffma2(b2f(fz.z),x2,az); az = ffma2(b2f(fz.w),x3,az);
                    an1= ffma2(b2f(fn.x),x0,an1);an1= ffma2(b2f(fn.y),x1,an1);an1= ffma2(b2f(fn.z),x2,an1);an1= ffma2(b2f(fn.w),x3,an1);
                }
            } else {
                #pragma unroll 2
                for (int j = 384; j < 512; j += 4) {
                    float4 fr = *(const float4*)(wr+j), fz = *(const float4*)(wz+j), fn = *(const float4*)(wn+j);
                    float2 x0 = s_c[(j-256)*16+bp], x1 = s_c[(j-255)*16+bp], x2 = s_c[(j-254)*16+bp], x3 = s_c[(j-253)*16+bp];
                    ar = ffma2(b2f(fr.x),x0,ar); ar = ffma2(b2f(fr.y),x1,ar); ar = ffma2(b2f(fr.z),x2,ar); ar = ffma2(b2f(fr.w),x3,ar);
                    az = ffma2(b2f(fz.x),x0,az); az = ffma2(b2f(fz.y),x1,az); az = ffma2(b2f(fz.z),x2,az); az = ffma2(b2f(fz.w),x3,az);
                    an1= ffma2(b2f(fn.x),x0,an1);an1= ffma2(b2f(fn.y),x1,an1);an1= ffma2(b2f(fn.z),x2,an1);an1= ffma2(b2f(fn.w),x3,an1);
                }
                #pragma unroll 2
                for (int j = 0; j < 256; j += 4) {
                    float4 fr = *(const float4*)(vr+j), fz = *(const float4*)(vz+j), fn = *(const float4*)(vn+j);
                    float2 x0 = s_h[(j+0)*16+bp], x1 = s_h[(j+1)*16+bp], x2 = s_h[(j+2)*16+bp], x3 = s_h[(j+3)*16+bp];
                    ar = ffma2(b2f(fr.x),x0,ar); ar = ffma2(b2f(fr.y),x1,ar); ar = ffma2(b2f(fr.z),x2,ar); ar = ffma2(b2f(fr.w),x3,ar);
                    az = ffma2(b2f(fz.x),x0,az); az = ffma2(b2f(fz.y),x1,az); az = ffma2(b2f(fz.z),x2,az); az = ffma2(b2f(fz.w),x3,az);
                    an2= ffma2(b2f(fn.x),x0,an2);an2= ffma2(b2f(fn.y),x1,an2);an2= ffma2(b2f(fn.z),x2,an2);an2= ffma2(b2f(fn.w),x3,an2);
                }
            }
            red[p][kl][bp][0] = ar; red[p][kl][bp][1] = az;
            red[p][kl][bp][2] = an1; red[p][kl][bp][3] = an2;
            __syncthreads();
            if (p == 0) {
                ar  = add2(ar,  red[1][kl][bp][0]);
                az  = add2(az,  red[1][kl][bp][1]);
                an1 = add2(an1, red[1][kl][bp][2]);
                an2 = add2(an2, red[1][kl][bp][3]);
                float br = bih[k] + bhh[k], bz = bih[HD+k] + bhh[HD+k];
                float bin = bih[2*HD+k], bhn = bhh[2*HD+k];
                float2 hprev = s_h[k*16 + bp];
                float rx = 1.f/(1.f + expf(-(ar.x + br)));
                float ry = 1.f/(1.f + expf(-(ar.y + br)));
                float zx = 1.f/(1.f + expf(-(az.x + bz)));
                float zy = 1.f/(1.f + expf(-(az.y + bz)));
                float nx = tanhf(an1.x + bin + rx*(an2.x + bhn));
                float ny = tanhf(an1.y + bin + ry*(an2.y + bhn));
                float2 hn = make_float2((1.f-zx)*nx + zx*hprev.x, (1.f-zy)*ny + zy*hprev.y);
                __stcg((float2*)(g_hT + (size_t)nxt*HD*BB) + (k*16 + bp), hn);
                g_obuf[((size_t)t*BB + 2*bp)*H2 + k]   = hn.x;
                g_obuf[((size_t)t*BB + 2*bp+1)*H2 + k] = hn.y;
            }
        }
        __syncthreads();
        if (tid == 0) { __threadfence(); atomicAdd(&g_bar, 1u);
            unsigned v; bar += NB;
            do { asm volatile("ld.acquire.gpu.b32 %0,[%1];":"=r"(v):"l"(&g_bar):"memory"); } while (v < bar);
        } else bar += NB;
        __syncthreads();

        // ---- phase H: hidden = relu(f1w1 @ h_new + b1), j-parallel ----
        {
            const float* hn = g_hT + (size_t)nxt*HD*BB;
            for (int i = tid; i < 2048; i += 256)
                ((float4*)sdyn)[i] = __ldcg((const float4*)hn + i);
            __syncthreads();
            int jj = tid >> 5, b = tid & 31;
            int j = g*8 + jj;
            float acc = 0.f;
            #pragma unroll 4
            for (int i4 = 0; i4 < 64; i4++) {
                float4 w = *(const float4*)(f1w1 + (size_t)j*HD + 4*i4);
                acc = fmaf(w.x, sdyn[(4*i4+0)*32+b], acc);
                acc = fmaf(w.y, sdyn[(4*i4+1)*32+b], acc);
                acc = fmaf(w.z, sdyn[(4*i4+2)*32+b], acc);
                acc = fmaf(w.w, sdyn[(4*i4+3)*32+b], acc);
            }
            __stcg(&g_hid[j*32 + b], fmaxf(acc + f1b1[j], 0.f));
        }
        __syncthreads();
        if (tid == 0) { __threadfence(); atomicAdd(&g_bar, 1u);
            unsigned v; bar += NB;
            do { asm volatile("ld.acquire.gpu.b32 %0,[%1];":"=r"(v):"l"(&g_bar):"memory"); } while (v < bar);
        } else bar += NB;
        __syncthreads();

        // ---- phase A: c1 + scores + softmax + ctx (block = batch b) ----
        int b = g;
        s_hid[tid] = __ldcg(&g_hid[tid*32 + b]);
        __syncthreads();
        if (tid < AD) {
            float acc = 0.f;
            #pragma unroll 8
            for (int i = 0; i < HD; i++) acc = fmaf(g_f1w2T[i*AD + tid], s_hid[i], acc);
            c1s[tid] = tanhf(acc + f1b2[tid]);
        }
        __syncthreads();
        {
            int s0 = 4*tid;
            const float* c2b = g_c2 + (size_t)b*AD*SQ;
            float4 sc = make_float4(0.f, 0.f, 0.f, 0.f);
            #pragma unroll 8
            for (int a = 0; a < AD; a++) {
                float4 v = *(const float4*)(c2b + (size_t)a*SQ + s0);
                float ca = c1s[a];
                sc.x = fmaf(ca, v.x, sc.x); sc.y = fmaf(ca, v.y, sc.y);
                sc.z = fmaf(ca, v.z, sc.z); sc.w = fmaf(ca, v.w, sc.w);
            }
            float mloc = fmaxf(fmaxf(sc.x, sc.y), fmaxf(sc.z, sc.w));
            #pragma unroll
            for (int o = 16; o; o >>= 1) mloc = fmaxf(mloc, __shfl_xor_sync(~0u, mloc, o));
            if ((tid & 31) == 0) rsh[tid >> 5] = mloc;
            __syncthreads();
            if (tid == 0) { float v = rsh[0]; for (int w = 1; w < 8; w++) v = fmaxf(v, rsh[w]); sh_mx = v; }
            __syncthreads();
            float mx = sh_mx;
            sc.x = __expf(sc.x - mx); sc.y = __expf(sc.y - mx);
            sc.z = __expf(sc.z - mx); sc.w = __expf(sc.w - mx);
            float sl = sc.x + sc.y + sc.z + sc.w;
            #pragma unroll
            for (int o = 16; o; o >>= 1) sl += __shfl_xor_sync(~0u, sl, o);
            if ((tid & 31) == 0) rsh[tid >> 5] = sl;
            __syncthreads();
            if (tid == 0) { float v = 0.f; for (int w = 0; w < 8; w++) v += rsh[w]; sh_sum = v; }
            __syncthreads();
            float inv = 1.f / sh_sum;
            *(float4*)&attw[s0] = make_float4(sc.x*inv, sc.y*inv, sc.z*inv, sc.w*inv);
        }
        __syncthreads();
        {
            int v = tid & 63, strip = tid >> 6;
            float2 a0 = z2, a1 = z2;
            #pragma unroll 4
            for (int ii = 0; ii < 256; ii++) {
                int s = strip*256 + ii;
                float aw = attw[s];
                float4 y = *(const float4*)(yenc + ((size_t)s*BB + b)*HD + 4*v);
                a0 = ffma2(b2f(aw), make_float2(y.x, y.y), a0);
                a1 = ffma2(b2f(aw), make_float2(y.z, y.w), a1);
            }
            cred[strip][v][0] = a0; cred[strip][v][1] = a1;
            __syncthreads();
            if (tid < 64) {
                float2 s0 = add2(add2(cred[0][tid][0], cred[1][tid][0]), add2(cred[2][tid][0], cred[3][tid][0]));
                float2 s1 = add2(add2(cred[0][tid][1], cred[1][tid][1]), add2(cred[2][tid][1], cred[3][tid][1]));
                float* cb = g_ctxT + (size_t)nxt*HD*BB;
                __stcg(&cb[(4*tid+0)*32 + b], s0.x);
                __stcg(&cb[(4*tid+1)*32 + b], s0.y);
                __stcg(&cb[(4*tid+2)*32 + b], s1.x);
                __stcg(&cb[(4*tid+3)*32 + b], s1.y);
                *(float4*)&g_obuf[((size_t)t*BB + b)*H2 + HD + 4*tid] = make_float4(s0.x, s0.y, s1.x, s1.y);
            }
        }
        __syncthreads();
        if (tid == 0) { __threadfence(); atomicAdd(&g_bar, 1u);
            unsigned v; bar += NB;
            do { asm volatile("ld.acquire.gpu.b32 %0,[%1];":"=r"(v):"l"(&g_bar):"memory"); } while (v < bar);
        } else bar += NB;
        __syncthreads();
    }
}

__global__ void k_fc1(const float* __restrict__ fc1b) {
    __shared__ float2 xsp[H2][8];
    int r0 = blockIdx.x*16, tid = threadIdx.x;
    float* xsf = (float*)xsp;
    for (int idx = tid; idx < 16*H2; idx += 256) {
        int r = idx >> 9, i = idx & 511;
        xsf[i*16 + r] = g_obuf[(size_t)(r0+r)*H2 + i];
    }
    __syncthreads();
    int j = tid; float bj = fc1b[j];
    float2 acc[8];
    #pragma unroll
    for (int p = 0; p < 8; p++) acc[p] = make_float2(bj, bj);
    for (int i = 0; i < H2; i++) {
        float2 wp = b2f(g_fc1wT[i*HD + j]);
        #pragma unroll
        for (int p = 0; p < 8; p++) acc[p] = ffma2(wp, xsp[i][p], acc[p]);
    }
    #pragma unroll
    for (int p = 0; p < 8; p++) {
        g_q[(size_t)(r0+2*p)*HD + j]   = fmaxf(acc[p].x, 0.f);
        g_q[(size_t)(r0+2*p+1)*HD + j] = fmaxf(acc[p].y, 0.f);
    }
}

__global__ void k_fc2(const float* __restrict__ fc2b, float* __restrict__ preds) {
    __shared__ float xs[HD][16];
    int tid = threadIdx.x;
    int n = blockIdx.x*128 + tid, rg = blockIdx.y;
    float bn = fc2b[n];
    for (int chunk = 0; chunk < 32; chunk++) {
        int rbase = rg*512 + chunk*16;
        __syncthreads();
        for (int idx = tid; idx < 16*HD; idx += 128) {
            int r = idx >> 8, k = idx & 255;
            xs[k][r] = g_q[(size_t)(rbase+r)*HD + k];
        }
        __syncthreads();
        float2 acc[8];
        #pragma unroll
        for (int p = 0; p < 8; p++) acc[p] = make_float2(0.f, 0.f);
        #pragma unroll 2
        for (int k = 0; k < HD; k++) {
            float2 wp = b2f(g_fc2wT[(size_t)k*VOCAB + n]);
            float4 x0 = *(const float4*)&xs[k][0];
            float4 x1 = *(const float4*)&xs[k][4];
            float4 x2 = *(const float4*)&xs[k][8];
            float4 x3 = *(const float4*)&xs[k][12];
            acc[0] = ffma2(wp, make_float2(x0.x, x0.y), acc[0]);
            acc[1] = ffma2(wp, make_float2(x0.z, x0.w), acc[1]);
            acc[2] = ffma2(wp, make_float2(x1.x, x1.y), acc[2]);
            acc[3] = ffma2(wp, make_float2(x1.z, x1.w), acc[3]);
            acc[4] = ffma2(wp, make_float2(x2.x, x2.y), acc[4]);
            acc[5] = ffma2(wp, make_float2(x2.z, x2.w), acc[5]);
            acc[6] = ffma2(wp, make_float2(x3.x, x3.y), acc[6]);
            acc[7] = ffma2(wp, make_float2(x3.z, x3.w), acc[7]);
        }
        #pragma unroll
        for (int p = 0; p < 8; p++) {
            preds[(size_t)(rbase+2*p)*VOCAB + n]   = acc[p].x + bn;
            preds[(size_t)(rbase+2*p+1)*VOCAB + n] = acc[p].y + bn;
        }
    }
}

__global__ void k_loss(const float* __restrict__ preds, const int* __restrict__ yout) {
    __shared__ float rsh[8];
    __shared__ float s_mx, s_sum;
    int row = blockIdx.x, tid = threadIdx.x;
    const float* p = preds + (size_t)row*VOCAB;
    float m = -1e30f;
    for (int v = tid; v < VOCAB; v += 256) m = fmaxf(m, p[v]);
    #pragma unroll
    for (int o = 16; o; o >>= 1) m = fmaxf(m, __shfl_xor_sync(~0u, m, o));
    if ((tid & 31) == 0) rsh[tid >> 5] = m;
    __syncthreads();
    if (tid == 0) { float v = rsh[0]; for (int w = 1; w < 8; w++) v = fmaxf(v, rsh[w]); s_mx = v; }
    __syncthreads();
    float mx = s_mx, s = 0.f;
    for (int v = tid; v < VOCAB; v += 256) s += __expf(p[v] - mx);
    #pragma unroll
    for (int o = 16; o; o >>= 1) s += __shfl_xor_sync(~0u, s, o);
    if ((tid & 31) == 0) rsh[tid >> 5] = s;
    __syncthreads();
    if (tid == 0) { float v = 0.f; for (int w = 0; w < 8; w++) v += rsh[w]; s_sum = v; }
    __syncthreads();
    if (tid == 0) {
        int tgt = yout[row];
        float msk = (tgt != 0) ? 1.f : 0.f;
        g_nll[row] = (mx + logf(s_sum) - p[tgt]) * msk;
        g_msk[row] = msk;
    }
}

__global__ void k_loss_final(float* __restrict__ out, int oi) {
    __shared__ float ra[8], rb[8];
    int tid = threadIdx.x;
    float a = 0.f, b = 0.f;
    for (int r = tid; r < ROWS_TOT; r += 256) { a += g_nll[r]; b += g_msk[r]; }
    #pragma unroll
    for (int o = 16; o; o >>= 1) { a += __shfl_xor_sync(~0u, a, o); b += __shfl_xor_sync(~0u, b, o); }
    if ((tid & 31) == 0) { ra[tid >> 5] = a; rb[tid >> 5] = b; }
    __syncthreads();
    if (tid == 0) {
        float sa = 0.f, sb = 0.f;
        for (int w = 0; w < 8; w++) { sa += ra[w]; sb += rb[w]; }
        out[oi] = sa / fmaxf(sb, 1.f);
    }
}

extern "C" void kernel_launch(void* const* d_in, const int* in_sizes, int n_in,
                              void* d_out, int out_size) {
    const int*   y_in  = (const int*)  d_in[0];
    const int*   y_out = (const int*)  d_in[1];
    const float* y_enc = (const float*)d_in[2];
    const float* emb   = (const float*)d_in[4];
    const float* f1_w1 = (const float*)d_in[5];
    const float* f1_b1 = (const float*)d_in[6];
    const float* f1_w2 = (const float*)d_in[7];
    const float* f1_b2 = (const float*)d_in[8];
    const float* f2_w1 = (const float*)d_in[9];
    const float* f2_b1 = (const float*)d_in[10];
    const float* f2_w2 = (const float*)d_in[11];
    const float* f2_b2 = (const float*)d_in[12];
    const float* g_wih = (const float*)d_in[13];
    const float* g_bih = (const float*)d_in[14];
    const float* g_whh = (const float*)d_in[15];
    const float* g_bhh = (const float*)d_in[16];
    const float* fc1_w = (const float*)d_in[17];
    const float* fc1_b = (const float*)d_in[18];
    const float* fc2_w = (const float*)d_in[19];
    const float* fc2_b = (const float*)d_in[20];

    float* preds = (float*)d_out;
    const long long TBV = (long long)TS*BB*VOCAB;

    static int cfg = 0;
    if (!cfg) { cudaFuncSetAttribute(k_loop, cudaFuncAttributeMaxDynamicSharedMemorySize, 65536); cfg = 1; }

    k_zero<<<(2*HD*BB + 255)/256, 256>>>();
    dim3 tb(32, 8);
    k_transpose<<<dim3(8,   8), tb>>>(f2_w1, 0, HD,    HD);
    k_transpose<<<dim3(8,   2), tb>>>(f2_w2, 1, AD,    HD);
    k_transpose<<<dim3(16,  8), tb>>>(fc1_w, 2, HD,    H2);
    k_transpose<<<dim3(8,   2), tb>>>(f1_w2, 3, AD,    HD);
    k_transpose<<<dim3(8, 1000), tb>>>(fc2_w, 4, VOCAB, HD);
    k_embT<<<TS, HD>>>(y_in, emb);
    k_c2<<<(SQ*BB)/16, 256>>>(y_enc, f2_b1, f2_b2);

    k_loop<<<NB, 256, 65536>>>(y_enc, g_wih, g_bih, g_whh, g_bhh, f1_w1, f1_b1, f1_b2);

    k_fc1<<<ROWS_TOT/16, 256>>>(fc1_b);
    k_fc2<<<dim3(VOCAB/128, 4), 128>>>(fc2_b, preds);
    if ((long long)out_size >= TBV + 1) {
        k_loss<<<ROWS_TOT, 256>>>(preds, y_out);
        k_loss_final<<<1, 256>>>(preds, (int)TBV);
    }
}

// round 8
// speedup vs baseline: 1.3916x; 1.1295x over previous
#include <cuda_runtime.h>
#include <math.h>

#define HD 256
#define AD 64
#define VOCAB 32000
#define TS 64
#define BB 32
#define SQ 1024
#define H2 512
#define ROWS_TOT (TS*BB)
#define NB 32

__device__ float g_embT[TS*HD*BB];             // [t][i][b]
__device__ float g_hT[2*HD*BB];                // ping-pong [p][k][b]
__device__ float g_ctxT[2*HD*BB];              // ping-pong [p][h][b]
__device__ float g_hid[HD*BB];                 // [j][b]
__device__ float g_c2[(size_t)BB*AD*SQ];       // [b][a][s]
__device__ float g_obuf[(size_t)ROWS_TOT*H2];
__device__ float g_qT[(size_t)HD*ROWS_TOT];    // fc1 out, k-major [k][r]
__device__ float g_f1w2T[HD*AD];
__device__ float g_f2w1T[HD*HD];
__device__ float g_f2w2T[HD*AD];
__device__ float g_fc1wT[H2*HD];
__device__ float g_fc2wT[(size_t)HD*VOCAB];
__device__ float g_nll[ROWS_TOT];
__device__ float g_msk[ROWS_TOT];
__device__ unsigned g_bar;

__device__ __forceinline__ float2 ffma2(float2 a, float2 b, float2 c) {
    union U { float2 f; unsigned long long u; };
    U ua, ub, uc, ud; ua.f = a; ub.f = b; uc.f = c;
    asm("fma.rn.f32x2 %0, %1, %2, %3;" : "=l"(ud.u) : "l"(ua.u), "l"(ub.u), "l"(uc.u));
    return ud.f;
}
__device__ __forceinline__ float2 b2f(float w) { return make_float2(w, w); }
__device__ __forceinline__ float2 add2(float2 a, float2 b) { return make_float2(a.x+b.x, a.y+b.y); }

// ---- launch 1: fused prep: zero + 4 small weight transposes + embT ----
__global__ void k_prep(const float* __restrict__ f2w1, const float* __restrict__ f2w2,
                       const float* __restrict__ f1w2, const float* __restrict__ fc1w,
                       const int* __restrict__ yin, const float* __restrict__ emb) {
    int bid = blockIdx.x, tid = threadIdx.x;
    if (bid == 0) {
        for (int i = tid; i < 2*HD*BB; i += 256) { g_hT[i] = 0.f; g_ctxT[i] = 0.f; }
        if (tid == 0) g_bar = 0u;
        return;
    }
    if (bid >= 225) {   // embT: 64 blocks
        int t = bid - 225, i = tid;
        for (int b = 0; b < BB; b++)
            g_embT[((size_t)t*HD + i)*BB + b] = emb[(size_t)yin[t*BB + b]*HD + i];
        return;
    }
    const float* src; float* dst; int rows, cols, nbx;
    int r = bid - 1;
    if (r < 64)       { src = f2w1; dst = g_f2w1T; rows = HD; cols = HD; nbx = 8; }
    else if (r < 80)  { r -= 64; src = f2w2; dst = g_f2w2T; rows = AD; cols = HD; nbx = 8; }
    else if (r < 96)  { r -= 80; src = f1w2; dst = g_f1w2T; rows = AD; cols = HD; nbx = 8; }
    else              { r -= 96; src = fc1w; dst = g_fc1wT; rows = HD; cols = H2; nbx = 16; }
    int bx = r % nbx, by = r / nbx;
    __shared__ float tile[32][33];
    int tx = tid & 31, ty = tid >> 5;
    int c0 = bx*32, r0 = by*32;
    for (int j = ty; j < 32; j += 8) {
        int rr = r0 + j, c = c0 + tx;
        if (rr < rows && c < cols) tile[j][tx] = src[(size_t)rr*cols + c];
    }
    __syncthreads();
    for (int j = ty; j < 32; j += 8) {
        int rr = r0 + tx, c = c0 + j;
        if (rr < rows && c < cols) dst[(size_t)c*rows + rr] = tile[tx][j];
    }
}

// ---- launch 2: fc2 weight transpose [VOCAB,HD] -> [HD,VOCAB] ----
__global__ void k_tr_fc2(const float* __restrict__ src) {
    __shared__ float tile[32][33];
    int c0 = blockIdx.x*32, r0 = blockIdx.y*32;
    int tx = threadIdx.x & 31, ty = threadIdx.x >> 5;
    for (int j = ty; j < 32; j += 8)
        tile[j][tx] = src[(size_t)(r0 + j)*HD + c0 + tx];
    __syncthreads();
    for (int j = ty; j < 32; j += 8)
        g_fc2wT[(size_t)(c0 + j)*VOCAB + r0 + tx] = tile[tx][j];
}

// ---- launch 3: c2 = tanh(relu(y_enc@f2w1^T+b1)@f2w2^T+b2), stored [b][a][s] ----
__global__ void k_c2(const float* __restrict__ yenc,
                     const float* __restrict__ b1, const float* __restrict__ b2) {
    __shared__ float2 ysp[HD][8];
    __shared__ float  hid[16][HD];
    int r0 = blockIdx.x*16, tid = threadIdx.x;
    float* ysf = (float*)ysp;
    for (int idx = tid; idx < 16*HD; idx += 256) {
        int r = idx >> 8, i = idx & 255;
        ysf[i*16 + r] = yenc[(size_t)(r0+r)*HD + i];
    }
    __syncthreads();
    {
        int j = tid; float bj = b1[j];
        float2 acc[8];
        #pragma unroll
        for (int p = 0; p < 8; p++) acc[p] = make_float2(bj, bj);
        for (int i = 0; i < HD; i++) {
            float2 wp = b2f(g_f2w1T[i*HD + j]);
            #pragma unroll
            for (int p = 0; p < 8; p++) acc[p] = ffma2(wp, ysp[i][p], acc[p]);
        }
        #pragma unroll
        for (int p = 0; p < 8; p++) {
            hid[2*p][j]   = fmaxf(acc[p].x, 0.f);
            hid[2*p+1][j] = fmaxf(acc[p].y, 0.f);
        }
    }
    __syncthreads();
    #pragma unroll
    for (int q = 0; q < 4; q++) {
        int o = tid + q*256, rr = o >> 6, a = o & 63;
        float acc = b2[a];
        for (int i = 0; i < HD; i++) acc = fmaf(hid[rr][i], g_f2w2T[i*AD + a], acc);
        int gr = r0 + rr, s = gr >> 5, b = gr & 31;
        g_c2[((size_t)b*AD + a)*SQ + s] = tanhf(acc);
    }
}

// ---- launch 4 (PROFILED): persistent decode loop, 32 blocks x 256 threads ----
__global__ void __launch_bounds__(256, 1)
k_loop(const float* __restrict__ yenc,
       const float* __restrict__ wih, const float* __restrict__ bih,
       const float* __restrict__ whh, const float* __restrict__ bhh,
       const float* __restrict__ f1w1, const float* __restrict__ f1b1,
       const float* __restrict__ f1b2) {
    extern __shared__ float sdyn[];
    float2* s_h = (float2*)sdyn;
    float2* s_c = (float2*)(sdyn + 8192);
    __shared__ float2 red[2][8][16][4];
    __shared__ float s_hid[HD];
    __shared__ float c1s[AD];
    __shared__ float attw[SQ];
    __shared__ float2 cred[4][64][2];
    __shared__ float rsh[8];
    __shared__ float sh_mx, sh_sum;

    int g = blockIdx.x, tid = threadIdx.x;
    int p = tid >> 7, kl = (tid >> 4) & 7, bp = tid & 15;
    int k = g*8 + kl;
    unsigned bar = 0;
    const float* wr = wih + (size_t)k*H2;
    const float* wz = wih + (size_t)(HD + k)*H2;
    const float* wn = wih + (size_t)(2*HD + k)*H2;
    const float* vr = whh + (size_t)k*HD;
    const float* vz = whh + (size_t)(HD + k)*HD;
    const float* vn = whh + (size_t)(2*HD + k)*HD;
    const float2 z2 = make_float2(0.f, 0.f);

    for (int t = 0; t < TS; t++) {
        int cur = t & 1, nxt = cur ^ 1;
        {
            const float4* hs = (const float4*)(g_hT + (size_t)cur*HD*BB);
            const float4* cs = (const float4*)(g_ctxT + (size_t)cur*HD*BB);
            float4* d0 = (float4*)s_h; float4* d1 = (float4*)s_c;
            for (int i = tid; i < 2048; i += 256) { d0[i] = __ldcg(hs + i); d1[i] = __ldcg(cs + i); }
        }
        __syncthreads();
        // ---- phase G: GRU ----
        {
            const float2* xe = (const float2*)(g_embT + (size_t)t*HD*BB);
            float2 ar = z2, az = ar, an1 = ar, an2 = ar;
            if (p == 0) {
                #pragma unroll 2
                for (int j = 0; j < 256; j += 4) {
                    float4 fr = *(const float4*)(wr+j), fz = *(const float4*)(wz+j), fn = *(const float4*)(wn+j);
                    float2 x0 = xe[(j+0)*16+bp], x1 = xe[(j+1)*16+bp], x2 = xe[(j+2)*16+bp], x3 = xe[(j+3)*16+bp];
                    ar = ffma2(b2f(fr.x),x0,ar); ar = ffma2(b2f(fr.y),x1,ar); ar = ffma2(b2f(fr.z),x2,ar); ar = ffma2(b2f(fr.w),x3,ar);
                    az = ffma2(b2f(fz.x),x0,az); az = ffma2(b2f(fz.y),x1,az); az = ffma2(b2f(fz.z),x2,az); az = ffma2(b2f(fz.w),x3,az);
                    an1= ffma2(b2f(fn.x),x0,an1);an1= ffma2(b2f(fn.y),x1,an1);an1= ffma2(b2f(fn.z),x2,an1);an1= ffma2(b2f(fn.w),x3,an1);
                }
                #pragma unroll 2
                for (int j = 256; j < 384; j += 4) {
                    float4 fr = *(const float4*)(wr+j), fz = *(const float4*)(wz+j), fn = *(const float4*)(wn+j);
                    float2 x0 = s_c[(j-256)*16+bp], x1 = s_c[(j-255)*16+bp], x2 = s_c[(j-254)*16+bp], x3 = s_c[(j-253)*16+bp];
                    ar = ffma2(b2f(fr.x),x0,ar); ar = ffma2(b2f(fr.y),x1,ar); ar = ffma2(b2f(fr.z),x2,ar); ar = ffma2(b2f(fr.w),x3,ar);
                    az = ffma2(b2f(fz.x),x0,az); az = ffma2(b2f(fz.y),x1,az); az = ffma2(b2f(fz.z),x2,az); az = ffma2(b2f(fz.w),x3,az);
                    an1= ffma2(b2f(fn.x),x0,an1);an1= ffma2(b2f(fn.y),x1,an1);an1= ffma2(b2f(fn.z),x2,an1);an1= ffma2(b2f(fn.w),x3,an1);
                }
            } else {
                #pragma unroll 2
                for (int j = 384; j < 512; j += 4) {
                    float4 fr = *(const float4*)(wr+j), fz = *(const float4*)(wz+j), fn = *(const float4*)(wn+j);
                    float2 x0 = s_c[(j-256)*16+bp], x1 = s_c[(j-255)*16+bp], x2 = s_c[(j-254)*16+bp], x3 = s_c[(j-253)*16+bp];
                    ar = ffma2(b2f(fr.x),x0,ar); ar = ffma2(b2f(fr.y),x1,ar); ar = ffma2(b2f(fr.z),x2,ar); ar = ffma2(b2f(fr.w),x3,ar);
                    az = ffma2(b2f(fz.x),x0,az); az = ffma2(b2f(fz.y),x1,az); az = ffma2(b2f(fz.z),x2,az); az = ffma2(b2f(fz.w),x3,az);
                    an1= ffma2(b2f(fn.x),x0,an1);an1= ffma2(b2f(fn.y),x1,an1);an1= ffma2(b2f(fn.z),x2,an1);an1= ffma2(b2f(fn.w),x3,an1);
                }
                #pragma unroll 2
                for (int j = 0; j < 256; j += 4) {
                    float4 fr = *(const float4*)(vr+j), fz = *(const float4*)(vz+j), fn = *(const float4*)(vn+j);
                    float2 x0 = s_h[(j+0)*16+bp], x1 = s_h[(j+1)*16+bp], x2 = s_h[(j+2)*16+bp], x3 = s_h[(j+3)*16+bp];
                    ar = ffma2(b2f(fr.x),x0,ar); ar = ffma2(b2f(fr.y),x1,ar); ar = ffma2(b2f(fr.z),x2,ar); ar = ffma2(b2f(fr.w),x3,ar);
                    az = ffma2(b2f(fz.x),x0,az); az = ffma2(b2f(fz.y),x1,az); az = ffma2(b2f(fz.z),x2,az); az = ffma2(b2f(fz.w),x3,az);
                    an2= ffma2(b2f(fn.x),x0,an2);an2= ffma2(b2f(fn.y),x1,an2);an2= ffma2(b2f(fn.z),x2,an2);an2= ffma2(b2f(fn.w),x3,an2);
                }
            }
            red[p][kl][bp][0] = ar; red[p][kl][bp][1] = az;
            red[p][kl][bp][2] = an1; red[p][kl][bp][3] = an2;
            __syncthreads();
            if (p == 0) {
                ar  = add2(ar,  red[1][kl][bp][0]);
                az  = add2(az,  red[1][kl][bp][1]);
                an1 = add2(an1, red[1][kl][bp][2]);
                an2 = add2(an2, red[1][kl][bp][3]);
                float br = bih[k] + bhh[k], bz = bih[HD+k] + bhh[HD+k];
                float bin = bih[2*HD+k], bhn = bhh[2*HD+k];
                float2 hprev = s_h[k*16 + bp];
                float rx = 1.f/(1.f + expf(-(ar.x + br)));
                float ry = 1.f/(1.f + expf(-(ar.y + br)));
                float zx = 1.f/(1.f + expf(-(az.x + bz)));
                float zy = 1.f/(1.f + expf(-(az.y + bz)));
                float nx = tanhf(an1.x + bin + rx*(an2.x + bhn));
                float ny = tanhf(an1.y + bin + ry*(an2.y + bhn));
                float2 hn = make_float2((1.f-zx)*nx + zx*hprev.x, (1.f-zy)*ny + zy*hprev.y);
                __stcg((float2*)(g_hT + (size_t)nxt*HD*BB) + (k*16 + bp), hn);
                g_obuf[((size_t)t*BB + 2*bp)*H2 + k]   = hn.x;
                g_obuf[((size_t)t*BB + 2*bp+1)*H2 + k] = hn.y;
            }
        }
        __syncthreads();
        if (tid == 0) { __threadfence(); atomicAdd(&g_bar, 1u);
            unsigned v; bar += NB;
            do { asm volatile("ld.acquire.gpu.b32 %0,[%1];":"=r"(v):"l"(&g_bar):"memory"); } while (v < bar);
        } else bar += NB;
        __syncthreads();

        // ---- phase H: hidden = relu(f1w1 @ h_new + b1) ----
        {
            const float* hn = g_hT + (size_t)nxt*HD*BB;
            for (int i = tid; i < 2048; i += 256)
                ((float4*)sdyn)[i] = __ldcg((const float4*)hn + i);
            __syncthreads();
            int jj = tid >> 5, b = tid & 31;
            int j = g*8 + jj;
            float acc = 0.f;
            #pragma unroll 4
            for (int i4 = 0; i4 < 64; i4++) {
                float4 w = *(const float4*)(f1w1 + (size_t)j*HD + 4*i4);
                acc = fmaf(w.x, sdyn[(4*i4+0)*32+b], acc);
                acc = fmaf(w.y, sdyn[(4*i4+1)*32+b], acc);
                acc = fmaf(w.z, sdyn[(4*i4+2)*32+b], acc);
                acc = fmaf(w.w, sdyn[(4*i4+3)*32+b], acc);
            }
            __stcg(&g_hid[j*32 + b], fmaxf(acc + f1b1[j], 0.f));
        }
        __syncthreads();
        if (tid == 0) { __threadfence(); atomicAdd(&g_bar, 1u);
            unsigned v; bar += NB;
            do { asm volatile("ld.acquire.gpu.b32 %0,[%1];":"=r"(v):"l"(&g_bar):"memory"); } while (v < bar);
        } else bar += NB;
        __syncthreads();

        // ---- phase A: c1 + scores + softmax + ctx (block = batch) ----
        int b = g;
        s_hid[tid] = __ldcg(&g_hid[tid*32 + b]);
        __syncthreads();
        if (tid < AD) {
            float acc = 0.f;
            #pragma unroll 8
            for (int i = 0; i < HD; i++) acc = fmaf(g_f1w2T[i*AD + tid], s_hid[i], acc);
            c1s[tid] = tanhf(acc + f1b2[tid]);
        }
        __syncthreads();
        {
            int s0 = 4*tid;
            const float* c2b = g_c2 + (size_t)b*AD*SQ;
            float4 sc = make_float4(0.f, 0.f, 0.f, 0.f);
            #pragma unroll 8
            for (int a = 0; a < AD; a++) {
                float4 v = *(const float4*)(c2b + (size_t)a*SQ + s0);
                float ca = c1s[a];
                sc.x = fmaf(ca, v.x, sc.x); sc.y = fmaf(ca, v.y, sc.y);
                sc.z = fmaf(ca, v.z, sc.z); sc.w = fmaf(ca, v.w, sc.w);
            }
            float mloc = fmaxf(fmaxf(sc.x, sc.y), fmaxf(sc.z, sc.w));
            #pragma unroll
            for (int o = 16; o; o >>= 1) mloc = fmaxf(mloc, __shfl_xor_sync(~0u, mloc, o));
            if ((tid & 31) == 0) rsh[tid >> 5] = mloc;
            __syncthreads();
            if (tid == 0) { float v = rsh[0]; for (int w = 1; w < 8; w++) v = fmaxf(v, rsh[w]); sh_mx = v; }
            __syncthreads();
            float mx = sh_mx;
            sc.x = __expf(sc.x - mx); sc.y = __expf(sc.y - mx);
            sc.z = __expf(sc.z - mx); sc.w = __expf(sc.w - mx);
            float sl = sc.x + sc.y + sc.z + sc.w;
            #pragma unroll
            for (int o = 16; o; o >>= 1) sl += __shfl_xor_sync(~0u, sl, o);
            if ((tid & 31) == 0) rsh[tid >> 5] = sl;
            __syncthreads();
            if (tid == 0) { float v = 0.f; for (int w = 0; w < 8; w++) v += rsh[w]; sh_sum = v; }
            __syncthreads();
            float inv = 1.f / sh_sum;
            *(float4*)&attw[s0] = make_float4(sc.x*inv, sc.y*inv, sc.z*inv, sc.w*inv);
        }
        __syncthreads();
        {
            int v = tid & 63, strip = tid >> 6;
            float2 a0 = z2, a1 = z2;
            #pragma unroll 4
            for (int ii = 0; ii < 256; ii++) {
                int s = strip*256 + ii;
                float aw = attw[s];
                float4 y = *(const float4*)(yenc + ((size_t)s*BB + b)*HD + 4*v);
                a0 = ffma2(b2f(aw), make_float2(y.x, y.y), a0);
                a1 = ffma2(b2f(aw), make_float2(y.z, y.w), a1);
            }
            cred[strip][v][0] = a0; cred[strip][v][1] = a1;
            __syncthreads();
            if (tid < 64) {
                float2 s0 = add2(add2(cred[0][tid][0], cred[1][tid][0]), add2(cred[2][tid][0], cred[3][tid][0]));
                float2 s1 = add2(add2(cred[0][tid][1], cred[1][tid][1]), add2(cred[2][tid][1], cred[3][tid][1]));
                float* cb = g_ctxT + (size_t)nxt*HD*BB;
                __stcg(&cb[(4*tid+0)*32 + b], s0.x);
                __stcg(&cb[(4*tid+1)*32 + b], s0.y);
                __stcg(&cb[(4*tid+2)*32 + b], s1.x);
                __stcg(&cb[(4*tid+3)*32 + b], s1.y);
                *(float4*)&g_obuf[((size_t)t*BB + b)*H2 + HD + 4*tid] = make_float4(s0.x, s0.y, s1.x, s1.y);
            }
        }
        __syncthreads();
        if (tid == 0) { __threadfence(); atomicAdd(&g_bar, 1u);
            unsigned v; bar += NB;
            do { asm volatile("ld.acquire.gpu.b32 %0,[%1];":"=r"(v):"l"(&g_bar):"memory"); } while (v < bar);
        } else bar += NB;
        __syncthreads();
    }
}

// ---- launch 5: fc1 -> g_qT (k-major) ----
__global__ void k_fc1(const float* __restrict__ fc1b) {
    __shared__ float2 xsp[H2][8];
    int r0 = blockIdx.x*16, tid = threadIdx.x;
    float* xsf = (float*)xsp;
    for (int idx = tid; idx < 16*H2; idx += 256) {
        int r = idx >> 9, i = idx & 511;
        xsf[i*16 + r] = g_obuf[(size_t)(r0+r)*H2 + i];
    }
    __syncthreads();
    int j = tid; float bj = fc1b[j];
    float2 acc[8];
    #pragma unroll
    for (int p = 0; p < 8; p++) acc[p] = make_float2(bj, bj);
    for (int i = 0; i < H2; i++) {
        float2 wp = b2f(g_fc1wT[i*HD + j]);
        #pragma unroll
        for (int p = 0; p < 8; p++) acc[p] = ffma2(wp, xsp[i][p], acc[p]);
    }
    #pragma unroll
    for (int p = 0; p < 8; p++) {
        g_qT[(size_t)j*ROWS_TOT + r0 + 2*p]   = fmaxf(acc[p].x, 0.f);
        g_qT[(size_t)j*ROWS_TOT + r0 + 2*p+1] = fmaxf(acc[p].y, 0.f);
    }
}

// ---- launch 6: tiled fc2: 64 rows x 128 cols per block ----
#define FBM 64
#define FBN 128
#define FKC 64
__global__ void __launch_bounds__(256) k_fc2(const float* __restrict__ fc2b, float* __restrict__ preds) {
    __shared__ float qs[FKC][FBM];
    __shared__ float ws[FKC][FBN];
    int tid = threadIdx.x;
    int nb = blockIdx.x * FBN, rb = blockIdx.y * FBM;
    int tm = tid >> 5, tn = tid & 31;
    float2 acc[8][2];
    #pragma unroll
    for (int i = 0; i < 8; i++) { acc[i][0] = make_float2(0.f,0.f); acc[i][1] = make_float2(0.f,0.f); }
    for (int kc = 0; kc < HD; kc += FKC) {
        __syncthreads();
        #pragma unroll
        for (int u = 0; u < 4; u++) {
            int idx = tid + u*256;                 // 1024 float4 of qs
            int kk = idx >> 4, rf = idx & 15;
            *(float4*)&qs[kk][rf*4] = *(const float4*)&g_qT[(size_t)(kc+kk)*ROWS_TOT + rb + rf*4];
        }
        #pragma unroll
        for (int u = 0; u < 8; u++) {
            int idx = tid + u*256;                 // 2048 float4 of ws
            int kk = idx >> 5, nf = idx & 31;
            *(float4*)&ws[kk][nf*4] = *(const float4*)&g_fc2wT[(size_t)(kc+kk)*VOCAB + nb + nf*4];
        }
        __syncthreads();
        #pragma unroll 2
        for (int kk = 0; kk < FKC; kk++) {
            float4 bfr = *(const float4*)&ws[kk][tn*4];
            float4 a0  = *(const float4*)&qs[kk][tm*8];
            float4 a1  = *(const float4*)&qs[kk][tm*8 + 4];
            float2 b01 = make_float2(bfr.x, bfr.y), b23 = make_float2(bfr.z, bfr.w);
            acc[0][0] = ffma2(b2f(a0.x), b01, acc[0][0]); acc[0][1] = ffma2(b2f(a0.x), b23, acc[0][1]);
            acc[1][0] = ffma2(b2f(a0.y), b01, acc[1][0]); acc[1][1] = ffma2(b2f(a0.y), b23, acc[1][1]);
            acc[2][0] = ffma2(b2f(a0.z), b01, acc[2][0]); acc[2][1] = ffma2(b2f(a0.z), b23, acc[2][1]);
            acc[3][0] = ffma2(b2f(a0.w), b01, acc[3][0]); acc[3][1] = ffma2(b2f(a0.w), b23, acc[3][1]);
            acc[4][0] = ffma2(b2f(a1.x), b01, acc[4][0]); acc[4][1] = ffma2(b2f(a1.x), b23, acc[4][1]);
            acc[5][0] = ffma2(b2f(a1.y), b01, acc[5][0]); acc[5][1] = ffma2(b2f(a1.y), b23, acc[5][1]);
            acc[6][0] = ffma2(b2f(a1.z), b01, acc[6][0]); acc[6][1] = ffma2(b2f(a1.z), b23, acc[6][1]);
            acc[7][0] = ffma2(b2f(a1.w), b01, acc[7][0]); acc[7][1] = ffma2(b2f(a1.w), b23, acc[7][1]);
        }
    }
    int n0 = nb + tn*4;
    float4 bv = *(const float4*)&fc2b[n0];
    #pragma unroll
    for (int i = 0; i < 8; i++) {
        float4 o = make_float4(acc[i][0].x + bv.x, acc[i][0].y + bv.y,
                               acc[i][1].x + bv.z, acc[i][1].y + bv.w);
        *(float4*)&preds[(size_t)(rb + tm*8 + i)*VOCAB + n0] = o;
    }
}

// ---- launch 7: single-pass online-softmax nll ----
__global__ void k_loss(const float* __restrict__ preds, const int* __restrict__ yout) {
    __shared__ float rm[8], rs[8];
    int row = blockIdx.x, tid = threadIdx.x;
    const float* p = preds + (size_t)row*VOCAB;
    float m = -1e30f, s = 0.f;
    for (int v = tid; v < VOCAB; v += 256) {
        float x = p[v];
        if (x <= m) s += __expf(x - m);
        else { s = s*__expf(m - x) + 1.f; m = x; }
    }
    #pragma unroll
    for (int o = 16; o; o >>= 1) {
        float mo = __shfl_xor_sync(~0u, m, o);
        float so = __shfl_xor_sync(~0u, s, o);
        float nm = fmaxf(m, mo);
        s = s*__expf(m - nm) + so*__expf(mo - nm);
        m = nm;
    }
    if ((tid & 31) == 0) { rm[tid >> 5] = m; rs[tid >> 5] = s; }
    __syncthreads();
    if (tid == 0) {
        float M = rm[0], S = rs[0];
        for (int w = 1; w < 8; w++) {
            float nm = fmaxf(M, rm[w]);
            S = S*__expf(M - nm) + rs[w]*__expf(rm[w] - nm);
            M = nm;
        }
        int tgt = yout[row];
        float msk = (tgt != 0) ? 1.f : 0.f;
        g_nll[row] = (M + logf(S) - p[tgt]) * msk;
        g_msk[row] = msk;
    }
}

// ---- launch 8: final loss reduce ----
__global__ void k_loss_final(float* __restrict__ out, int oi) {
    __shared__ float ra[8], rb[8];
    int tid = threadIdx.x;
    float a = 0.f, b = 0.f;
    for (int r = tid; r < ROWS_TOT; r += 256) { a += g_nll[r]; b += g_msk[r]; }
    #pragma unroll
    for (int o = 16; o; o >>= 1) { a += __shfl_xor_sync(~0u, a, o); b += __shfl_xor_sync(~0u, b, o); }
    if ((tid & 31) == 0) { ra[tid >> 5] = a; rb[tid >> 5] = b; }
    __syncthreads();
    if (tid == 0) {
        float sa = 0.f, sb = 0.f;
        for (int w = 0; w < 8; w++) { sa += ra[w]; sb += rb[w]; }
        out[oi] = sa / fmaxf(sb, 1.f);
    }
}

extern "C" void kernel_launch(void* const* d_in, const int* in_sizes, int n_in,
                              void* d_out, int out_size) {
    const int*   y_in  = (const int*)  d_in[0];
    const int*   y_out = (const int*)  d_in[1];
    const float* y_enc = (const float*)d_in[2];
    const float* emb   = (const float*)d_in[4];
    const float* f1_w1 = (const float*)d_in[5];
    const float* f1_b1 = (const float*)d_in[6];
    const float* f1_w2 = (const float*)d_in[7];
    const float* f1_b2 = (const float*)d_in[8];
    const float* f2_w1 = (const float*)d_in[9];
    const float* f2_b1 = (const float*)d_in[10];
    const float* f2_w2 = (const float*)d_in[11];
    const float* f2_b2 = (const float*)d_in[12];
    const float* g_wih = (const float*)d_in[13];
    const float* g_bih = (const float*)d_in[14];
    const float* g_whh = (const float*)d_in[15];
    const float* g_bhh = (const float*)d_in[16];
    const float* fc1_w = (const float*)d_in[17];
    const float* fc1_b = (const float*)d_in[18];
    const float* fc2_w = (const float*)d_in[19];
    const float* fc2_b = (const float*)d_in[20];

    float* preds = (float*)d_out;
    const long long TBV = (long long)TS*BB*VOCAB;

    cudaFuncSetAttribute(k_loop, cudaFuncAttributeMaxDynamicSharedMemorySize, 65536);

    k_prep<<<289, 256>>>(f2_w1, f2_w2, f1_w2, fc1_w, y_in, emb);          // 1
    k_tr_fc2<<<dim3(8, 1000), 256>>>(fc2_w);                               // 2
    k_c2<<<(SQ*BB)/16, 256>>>(y_enc, f2_b1, f2_b2);                        // 3
    k_loop<<<NB, 256, 65536>>>(y_enc, g_wih, g_bih, g_whh, g_bhh,
                               f1_w1, f1_b1, f1_b2);                       // 4 <- profiled
    k_fc1<<<ROWS_TOT/16, 256>>>(fc1_b);                                    // 5
    k_fc2<<<dim3(VOCAB/FBN, ROWS_TOT/FBM), 256>>>(fc2_b, preds);           // 6
    if ((long long)out_size >= TBV + 1) {
        k_loss<<<ROWS_TOT, 256>>>(preds, y_out);                           // 7
        k_loss_final<<<1, 256>>>(preds, (int)TBV);                         // 8
    }
}

// round 9
// speedup vs baseline: 1.9368x; 1.3918x over previous
#include <cuda_runtime.h>
#include <math.h>

#define HD 256
#define AD 64
#define VOCAB 32000
#define TS 64
#define BB 32
#define SQ 1024
#define H2 512
#define ROWS_TOT (TS*BB)
#define NB 64

__device__ float g_embT[TS*HD*BB];             // [t][i][b]
__device__ float g_hT[2*HD*BB];                // ping-pong [p][k][b]
__device__ float g_ctxT[2*HD*BB];              // ping-pong [p][h][b]
__device__ float g_hid[HD*BB];                 // [j][b]
__device__ float g_c2[(size_t)BB*AD*SQ];       // [b][a][s]
__device__ float g_obuf[(size_t)ROWS_TOT*H2];
__device__ float g_qT[(size_t)HD*ROWS_TOT];    // fc1 out, k-major [k][r]
__device__ float g_f1w2T[HD*AD];
__device__ float g_f2w1T[HD*HD];
__device__ float g_f2w2T[HD*AD];
__device__ float g_fc1wT[H2*HD];
__device__ float g_fc2wT[(size_t)HD*VOCAB];
__device__ float g_nll[ROWS_TOT];
__device__ float g_msk[ROWS_TOT];
__device__ unsigned g_bar;

__device__ __forceinline__ float2 ffma2(float2 a, float2 b, float2 c) {
    union U { float2 f; unsigned long long u; };
    U ua, ub, uc, ud; ua.f = a; ub.f = b; uc.f = c;
    asm("fma.rn.f32x2 %0, %1, %2, %3;" : "=l"(ud.u) : "l"(ua.u), "l"(ub.u), "l"(uc.u));
    return ud.f;
}
__device__ __forceinline__ float2 b2f(float w) { return make_float2(w, w); }
__device__ __forceinline__ float2 add2(float2 a, float2 b) { return make_float2(a.x+b.x, a.y+b.y); }

// ---- launch 1: fused prep: zero + 4 small weight transposes + embT ----
__global__ void k_prep(const float* __restrict__ f2w1, const float* __restrict__ f2w2,
                       const float* __restrict__ f1w2, const float* __restrict__ fc1w,
                       const int* __restrict__ yin, const float* __restrict__ emb) {
    int bid = blockIdx.x, tid = threadIdx.x;
    if (bid == 0) {
        for (int i = tid; i < 2*HD*BB; i += 256) { g_hT[i] = 0.f; g_ctxT[i] = 0.f; }
        if (tid == 0) g_bar = 0u;
        return;
    }
    if (bid >= 225) {   // embT: 64 blocks
        int t = bid - 225, i = tid;
        for (int b = 0; b < BB; b++)
            g_embT[((size_t)t*HD + i)*BB + b] = emb[(size_t)yin[t*BB + b]*HD + i];
        return;
    }
    const float* src; float* dst; int rows, cols, nbx;
    int r = bid - 1;
    if (r < 64)       { src = f2w1; dst = g_f2w1T; rows = HD; cols = HD; nbx = 8; }
    else if (r < 80)  { r -= 64; src = f2w2; dst = g_f2w2T; rows = AD; cols = HD; nbx = 8; }
    else if (r < 96)  { r -= 80; src = f1w2; dst = g_f1w2T; rows = AD; cols = HD; nbx = 8; }
    else              { r -= 96; src = fc1w; dst = g_fc1wT; rows = HD; cols = H2; nbx = 16; }
    int bx = r % nbx, by = r / nbx;
    __shared__ float tile[32][33];
    int tx = tid & 31, ty = tid >> 5;
    int c0 = bx*32, r0 = by*32;
    for (int j = ty; j < 32; j += 8) {
        int rr = r0 + j, c = c0 + tx;
        if (rr < rows && c < cols) tile[j][tx] = src[(size_t)rr*cols + c];
    }
    __syncthreads();
    for (int j = ty; j < 32; j += 8) {
        int rr = r0 + tx, c = c0 + j;
        if (rr < rows && c < cols) dst[(size_t)c*rows + rr] = tile[tx][j];
    }
}

// ---- launch 2: fc2 weight transpose ----
__global__ void k_tr_fc2(const float* __restrict__ src) {
    __shared__ float tile[32][33];
    int c0 = blockIdx.x*32, r0 = blockIdx.y*32;
    int tx = threadIdx.x & 31, ty = threadIdx.x >> 5;
    for (int j = ty; j < 32; j += 8)
        tile[j][tx] = src[(size_t)(r0 + j)*HD + c0 + tx];
    __syncthreads();
    for (int j = ty; j < 32; j += 8)
        g_fc2wT[(size_t)(c0 + j)*VOCAB + r0 + tx] = tile[tx][j];
}

// ---- launch 3: c2, stored [b][a][s] ----
__global__ void k_c2(const float* __restrict__ yenc,
                     const float* __restrict__ b1, const float* __restrict__ b2) {
    __shared__ float2 ysp[HD][8];
    __shared__ float  hid[16][HD];
    int r0 = blockIdx.x*16, tid = threadIdx.x;
    float* ysf = (float*)ysp;
    for (int idx = tid; idx < 16*HD; idx += 256) {
        int r = idx >> 8, i = idx & 255;
        ysf[i*16 + r] = yenc[(size_t)(r0+r)*HD + i];
    }
    __syncthreads();
    {
        int j = tid; float bj = b1[j];
        float2 acc[8];
        #pragma unroll
        for (int p = 0; p < 8; p++) acc[p] = make_float2(bj, bj);
        for (int i = 0; i < HD; i++) {
            float2 wp = b2f(g_f2w1T[i*HD + j]);
            #pragma unroll
            for (int p = 0; p < 8; p++) acc[p] = ffma2(wp, ysp[i][p], acc[p]);
        }
        #pragma unroll
        for (int p = 0; p < 8; p++) {
            hid[2*p][j]   = fmaxf(acc[p].x, 0.f);
            hid[2*p+1][j] = fmaxf(acc[p].y, 0.f);
        }
    }
    __syncthreads();
    #pragma unroll
    for (int q = 0; q < 4; q++) {
        int o = tid + q*256, rr = o >> 6, a = o & 63;
        float acc = b2[a];
        for (int i = 0; i < HD; i++) acc = fmaf(hid[rr][i], g_f2w2T[i*AD + a], acc);
        int gr = r0 + rr, s = gr >> 5, b = gr & 31;
        g_c2[((size_t)b*AD + a)*SQ + s] = tanhf(acc);
    }
}

// ---- launch 4 (PROFILED): persistent decode loop, 64 blocks x 256 threads ----
// Dynamic smem: 96KB = [emb 32KB | ctx 32KB | h 32KB], float2-indexed sm2[p*16+bp], p in [0,768)
__global__ void __launch_bounds__(256, 1)
k_loop(const float* __restrict__ yenc,
       const float* __restrict__ wih, const float* __restrict__ bih,
       const float* __restrict__ whh, const float* __restrict__ bhh,
       const float* __restrict__ f1w1, const float* __restrict__ f1b1,
       const float* __restrict__ f1b2) {
    extern __shared__ float sdyn[];
    float2* sm2 = (float2*)sdyn;
    __shared__ float2 red[4][4][16][4];   // [ph][kl][bp][gate] 8KB
    __shared__ float hred[256];
    __shared__ float s_hid[HD];
    __shared__ float c1s[AD];
    __shared__ float attw[SQ];
    __shared__ float2 cred[8][32][2];     // 4KB
    __shared__ float rsh[8];
    __shared__ float sh_mx, sh_sum;

    int g = blockIdx.x, tid = threadIdx.x;
    int kl = tid >> 6, ph = (tid >> 4) & 3, bp = tid & 15;
    int k = g*4 + kl;
    int ab = g >> 1, half = g & 1;        // phase-A batch + h-half
    unsigned bar = 0;
    const float* wihR = wih + (size_t)k*H2;
    const float* wihZ = wih + (size_t)(HD + k)*H2;
    const float* wihN = wih + (size_t)(2*HD + k)*H2;
    const float* whhR = whh + (size_t)k*HD;
    const float* whhZ = whh + (size_t)(HD + k)*HD;
    const float* whhN = whh + (size_t)(2*HD + k)*HD;
    const float2 z2 = make_float2(0.f, 0.f);

    for (int t = 0; t < TS; t++) {
        int cur = t & 1, nxt = cur ^ 1;
        // ---- stage emb(t) | ctx(cur) | h(cur) into smem ----
        {
            float4* d = (float4*)sdyn;
            const float4* se = (const float4*)(g_embT) + (size_t)t*2048;
            const float4* sc = (const float4*)(g_ctxT + (size_t)cur*HD*BB);
            const float4* sh = (const float4*)(g_hT   + (size_t)cur*HD*BB);
            for (int i = tid; i < 2048; i += 256) {
                d[i]        = se[i];
                d[2048 + i] = __ldcg(sc + i);
                d[4096 + i] = __ldcg(sh + i);
            }
        }
        __syncthreads();
        // ---- phase G: GRU, 4 k's per block, 4-way input split ----
        {
            float2 ar = z2, az = z2, ani = z2, anh = z2;
            int pst = ph*192, pen = pst + 192;
            int mid = pen < 512 ? pen : (pst > 512 ? pst : 512);
            for (int p0 = pst; p0 < mid; p0 += 4) {        // ih part (emb+ctx)
                float2 x0 = sm2[(p0+0)*16+bp], x1 = sm2[(p0+1)*16+bp];
                float2 x2 = sm2[(p0+2)*16+bp], x3 = sm2[(p0+3)*16+bp];
                float4 fr = *(const float4*)(wihR + p0);
                float4 fz = *(const float4*)(wihZ + p0);
                float4 fn = *(const float4*)(wihN + p0);
                ar = ffma2(b2f(fr.x),x0,ar); ar = ffma2(b2f(fr.y),x1,ar); ar = ffma2(b2f(fr.z),x2,ar); ar = ffma2(b2f(fr.w),x3,ar);
                az = ffma2(b2f(fz.x),x0,az); az = ffma2(b2f(fz.y),x1,az); az = ffma2(b2f(fz.z),x2,az); az = ffma2(b2f(fz.w),x3,az);
                ani= ffma2(b2f(fn.x),x0,ani);ani= ffma2(b2f(fn.y),x1,ani);ani= ffma2(b2f(fn.z),x2,ani);ani= ffma2(b2f(fn.w),x3,ani);
            }
            for (int p0 = mid; p0 < pen; p0 += 4) {        // hh part (h)
                float2 x0 = sm2[(p0+0)*16+bp], x1 = sm2[(p0+1)*16+bp];
                float2 x2 = sm2[(p0+2)*16+bp], x3 = sm2[(p0+3)*16+bp];
                int q = p0 - 512;
                float4 fr = *(const float4*)(whhR + q);
                float4 fz = *(const float4*)(whhZ + q);
                float4 fn = *(const float4*)(whhN + q);
                ar = ffma2(b2f(fr.x),x0,ar); ar = ffma2(b2f(fr.y),x1,ar); ar = ffma2(b2f(fr.z),x2,ar); ar = ffma2(b2f(fr.w),x3,ar);
                az = ffma2(b2f(fz.x),x0,az); az = ffma2(b2f(fz.y),x1,az); az = ffma2(b2f(fz.z),x2,az); az = ffma2(b2f(fz.w),x3,az);
                anh= ffma2(b2f(fn.x),x0,anh);anh= ffma2(b2f(fn.y),x1,anh);anh= ffma2(b2f(fn.z),x2,anh);anh= ffma2(b2f(fn.w),x3,anh);
            }
            red[ph][kl][bp][0] = ar; red[ph][kl][bp][1] = az;
            red[ph][kl][bp][2] = ani; red[ph][kl][bp][3] = anh;
        }
        __syncthreads();
        if (tid < 64) {
            int kk = tid >> 4, bq = tid & 15;
            int kg = g*4 + kk;
            float2 ar = z2, az = z2, ani = z2, anh = z2;
            #pragma unroll
            for (int q = 0; q < 4; q++) {
                ar  = add2(ar,  red[q][kk][bq][0]);
                az  = add2(az,  red[q][kk][bq][1]);
                ani = add2(ani, red[q][kk][bq][2]);
                anh = add2(anh, red[q][kk][bq][3]);
            }
            float br = bih[kg] + bhh[kg], bz = bih[HD+kg] + bhh[HD+kg];
            float bin = bih[2*HD+kg], bhn = bhh[2*HD+kg];
            float2 hprev = sm2[(512 + kg)*16 + bq];
            float rx = 1.f/(1.f + expf(-(ar.x + br)));
            float ry = 1.f/(1.f + expf(-(ar.y + br)));
            float zx = 1.f/(1.f + expf(-(az.x + bz)));
            float zy = 1.f/(1.f + expf(-(az.y + bz)));
            float nx = tanhf(ani.x + bin + rx*(anh.x + bhn));
            float ny = tanhf(ani.y + bin + ry*(anh.y + bhn));
            float2 hn = make_float2((1.f-zx)*nx + zx*hprev.x, (1.f-zy)*ny + zy*hprev.y);
            __stcg((float2*)(g_hT + (size_t)nxt*HD*BB) + (kg*16 + bq), hn);
            g_obuf[((size_t)t*BB + 2*bq)*H2 + kg]   = hn.x;
            g_obuf[((size_t)t*BB + 2*bq+1)*H2 + kg] = hn.y;
        }
        __syncthreads();
        if (tid == 0) { __threadfence(); atomicAdd(&g_bar, 1u);
            unsigned v; bar += NB;
            do { asm volatile("ld.acquire.gpu.b32 %0,[%1];":"=r"(v):"l"(&g_bar):"memory"); } while (v < bar);
        } else bar += NB;
        __syncthreads();

        // ---- phase H: hidden = relu(f1w1 @ h_new + b1), 4 j's per block ----
        {
            float4* d = (float4*)sdyn;
            const float4* hn = (const float4*)(g_hT + (size_t)nxt*HD*BB);
            for (int i = tid; i < 2048; i += 256) d[i] = __ldcg(hn + i);
            __syncthreads();
            int hf = tid >> 7, jj = (tid >> 5) & 3, b = tid & 31;
            int j = g*4 + jj;
            const float* w = f1w1 + (size_t)j*HD + hf*128;
            float acc = 0.f;
            #pragma unroll 8
            for (int i4 = 0; i4 < 32; i4++) {
                float4 w4 = *(const float4*)(w + 4*i4);
                int ib = (hf*128 + 4*i4)*32 + b;
                acc = fmaf(w4.x, sdyn[ib],      acc);
                acc = fmaf(w4.y, sdyn[ib+32],   acc);
                acc = fmaf(w4.z, sdyn[ib+64],   acc);
                acc = fmaf(w4.w, sdyn[ib+96],   acc);
            }
            hred[tid] = acc;
        }
        __syncthreads();
        if (tid < 128) {
            int j = g*4 + (tid >> 5), b = tid & 31;
            float v = hred[tid] + hred[tid + 128] + f1b1[j];
            __stcg(&g_hid[j*32 + b], fmaxf(v, 0.f));
        }
        __syncthreads();
        if (tid == 0) { __threadfence(); atomicAdd(&g_bar, 1u);
            unsigned v; bar += NB;
            do { asm volatile("ld.acquire.gpu.b32 %0,[%1];":"=r"(v):"l"(&g_bar):"memory"); } while (v < bar);
        } else bar += NB;
        __syncthreads();

        // ---- phase A: c1 + scores + softmax (dup per half) + ctx (h-split) ----
        s_hid[tid] = __ldcg(&g_hid[tid*32 + ab]);
        __syncthreads();
        if (tid < AD) {
            float acc = 0.f;
            #pragma unroll 8
            for (int i = 0; i < HD; i++) acc = fmaf(g_f1w2T[i*AD + tid], s_hid[i], acc);
            c1s[tid] = tanhf(acc + f1b2[tid]);
        }
        __syncthreads();
        {
            int s0 = 4*tid;
            const float* c2b = g_c2 + (size_t)ab*AD*SQ;
            float4 sc = make_float4(0.f, 0.f, 0.f, 0.f);
            for (int a0 = 0; a0 < AD; a0 += 8) {
                float4 v[8];
                #pragma unroll
                for (int u = 0; u < 8; u++) v[u] = *(const float4*)(c2b + (size_t)(a0+u)*SQ + s0);
                #pragma unroll
                for (int u = 0; u < 8; u++) {
                    float ca = c1s[a0+u];
                    sc.x = fmaf(ca, v[u].x, sc.x); sc.y = fmaf(ca, v[u].y, sc.y);
                    sc.z = fmaf(ca, v[u].z, sc.z); sc.w = fmaf(ca, v[u].w, sc.w);
                }
            }
            float mloc = fmaxf(fmaxf(sc.x, sc.y), fmaxf(sc.z, sc.w));
            #pragma unroll
            for (int o = 16; o; o >>= 1) mloc = fmaxf(mloc, __shfl_xor_sync(~0u, mloc, o));
            if ((tid & 31) == 0) rsh[tid >> 5] = mloc;
            __syncthreads();
            if (tid == 0) { float v = rsh[0]; for (int w = 1; w < 8; w++) v = fmaxf(v, rsh[w]); sh_mx = v; }
            __syncthreads();
            float mx = sh_mx;
            sc.x = __expf(sc.x - mx); sc.y = __expf(sc.y - mx);
            sc.z = __expf(sc.z - mx); sc.w = __expf(sc.w - mx);
            float sl = sc.x + sc.y + sc.z + sc.w;
            #pragma unroll
            for (int o = 16; o; o >>= 1) sl += __shfl_xor_sync(~0u, sl, o);
            if ((tid & 31) == 0) rsh[tid >> 5] = sl;
            __syncthreads();
            if (tid == 0) { float v = 0.f; for (int w = 0; w < 8; w++) v += rsh[w]; sh_sum = v; }
            __syncthreads();
            float inv = 1.f / sh_sum;
            *(float4*)&attw[s0] = make_float4(sc.x*inv, sc.y*inv, sc.z*inv, sc.w*inv);
        }
        __syncthreads();
        {
            int v = tid & 31, strip = tid >> 5;
            int h0 = half*128;
            float2 a0 = z2, a1 = z2;
            for (int o8 = 0; o8 < 128; o8 += 8) {
                float4 y[8]; float aw[8];
                #pragma unroll
                for (int u = 0; u < 8; u++) {
                    int s = strip*128 + o8 + u;
                    y[u] = *(const float4*)(yenc + ((size_t)s*BB + ab)*HD + h0 + 4*v);
                    aw[u] = attw[s];
                }
                #pragma unroll
                for (int u = 0; u < 8; u++) {
                    a0 = ffma2(b2f(aw[u]), make_float2(y[u].x, y[u].y), a0);
                    a1 = ffma2(b2f(aw[u]), make_float2(y[u].z, y[u].w), a1);
                }
            }
            cred[strip][v][0] = a0; cred[strip][v][1] = a1;
            __syncthreads();
            if (tid < 32) {
                float2 s0 = z2, s1 = z2;
                #pragma unroll
                for (int w = 0; w < 8; w++) { s0 = add2(s0, cred[w][tid][0]); s1 = add2(s1, cred[w][tid][1]); }
                int hh = h0 + 4*tid;
                float* cb = g_ctxT + (size_t)nxt*HD*BB;
                __stcg(&cb[(hh+0)*32 + ab], s0.x);
                __stcg(&cb[(hh+1)*32 + ab], s0.y);
                __stcg(&cb[(hh+2)*32 + ab], s1.x);
                __stcg(&cb[(hh+3)*32 + ab], s1.y);
                *(float4*)&g_obuf[((size_t)t*BB + ab)*H2 + HD + hh] = make_float4(s0.x, s0.y, s1.x, s1.y);
            }
        }
        __syncthreads();
        if (tid == 0) { __threadfence(); atomicAdd(&g_bar, 1u);
            unsigned v; bar += NB;
            do { asm volatile("ld.acquire.gpu.b32 %0,[%1];":"=r"(v):"l"(&g_bar):"memory"); } while (v < bar);
        } else bar += NB;
        __syncthreads();
    }
}

// ---- launch 5: fc1 -> g_qT (k-major) ----
__global__ void k_fc1(const float* __restrict__ fc1b) {
    __shared__ float2 xsp[H2][8];
    int r0 = blockIdx.x*16, tid = threadIdx.x;
    float* xsf = (float*)xsp;
    for (int idx = tid; idx < 16*H2; idx += 256) {
        int r = idx >> 9, i = idx & 511;
        xsf[i*16 + r] = g_obuf[(size_t)(r0+r)*H2 + i];
    }
    __syncthreads();
    int j = tid; float bj = fc1b[j];
    float2 acc[8];
    #pragma unroll
    for (int p = 0; p < 8; p++) acc[p] = make_float2(bj, bj);
    for (int i = 0; i < H2; i++) {
        float2 wp = b2f(g_fc1wT[i*HD + j]);
        #pragma unroll
        for (int p = 0; p < 8; p++) acc[p] = ffma2(wp, xsp[i][p], acc[p]);
    }
    #pragma unroll
    for (int p = 0; p < 8; p++) {
        g_qT[(size_t)j*ROWS_TOT + r0 + 2*p]   = fmaxf(acc[p].x, 0.f);
        g_qT[(size_t)j*ROWS_TOT + r0 + 2*p+1] = fmaxf(acc[p].y, 0.f);
    }
}

// ---- launch 6: tiled fc2 ----
#define FBM 64
#define FBN 128
#define FKC 64
__global__ void __launch_bounds__(256) k_fc2(const float* __restrict__ fc2b, float* __restrict__ preds) {
    __shared__ float qs[FKC][FBM];
    __shared__ float ws[FKC][FBN];
    int tid = threadIdx.x;
    int nb = blockIdx.x * FBN, rb = blockIdx.y * FBM;
    int tm = tid >> 5, tn = tid & 31;
    float2 acc[8][2];
    #pragma unroll
    for (int i = 0; i < 8; i++) { acc[i][0] = make_float2(0.f,0.f); acc[i][1] = make_float2(0.f,0.f); }
    for (int kc = 0; kc < HD; kc += FKC) {
        __syncthreads();
        #pragma unroll
        for (int u = 0; u < 4; u++) {
            int idx = tid + u*256;
            int kk = idx >> 4, rf = idx & 15;
            *(float4*)&qs[kk][rf*4] = *(const float4*)&g_qT[(size_t)(kc+kk)*ROWS_TOT + rb + rf*4];
        }
        #pragma unroll
        for (int u = 0; u < 8; u++) {
            int idx = tid + u*256;
            int kk = idx >> 5, nf = idx & 31;
            *(float4*)&ws[kk][nf*4] = *(const float4*)&g_fc2wT[(size_t)(kc+kk)*VOCAB + nb + nf*4];
        }
        __syncthreads();
        #pragma unroll 2
        for (int kk = 0; kk < FKC; kk++) {
            float4 bfr = *(const float4*)&ws[kk][tn*4];
            float4 a0  = *(const float4*)&qs[kk][tm*8];
            float4 a1  = *(const float4*)&qs[kk][tm*8 + 4];
            float2 b01 = make_float2(bfr.x, bfr.y), b23 = make_float2(bfr.z, bfr.w);
            acc[0][0] = ffma2(b2f(a0.x), b01, acc[0][0]); acc[0][1] = ffma2(b2f(a0.x), b23, acc[0][1]);
            acc[1][0] = ffma2(b2f(a0.y), b01, acc[1][0]); acc[1][1] = ffma2(b2f(a0.y), b23, acc[1][1]);
            acc[2][0] = ffma2(b2f(a0.z), b01, acc[2][0]); acc[2][1] = ffma2(b2f(a0.z), b23, acc[2][1]);
            acc[3][0] = ffma2(b2f(a0.w), b01, acc[3][0]); acc[3][1] = ffma2(b2f(a0.w), b23, acc[3][1]);
            acc[4][0] = ffma2(b2f(a1.x), b01, acc[4][0]); acc[4][1] = ffma2(b2f(a1.x), b23, acc[4][1]);
            acc[5][0] = ffma2(b2f(a1.y), b01, acc[5][0]); acc[5][1] = ffma2(b2f(a1.y), b23, acc[5][1]);
            acc[6][0] = ffma2(b2f(a1.z), b01, acc[6][0]); acc[6][1] = ffma2(b2f(a1.z), b23, acc[6][1]);
            acc[7][0] = ffma2(b2f(a1.w), b01, acc[7][0]); acc[7][1] = ffma2(b2f(a1.w), b23, acc[7][1]);
        }
    }
    int n0 = nb + tn*4;
    float4 bv = *(const float4*)&fc2b[n0];
    #pragma unroll
    for (int i = 0; i < 8; i++) {
        float4 o = make_float4(acc[i][0].x + bv.x, acc[i][0].y + bv.y,
                               acc[i][1].x + bv.z, acc[i][1].y + bv.w);
        *(float4*)&preds[(size_t)(rb + tm*8 + i)*VOCAB + n0] = o;
    }
}

// ---- launch 7: single-pass online-softmax nll ----
__global__ void k_loss(const float* __restrict__ preds, const int* __restrict__ yout) {
    __shared__ float rm[8], rs[8];
    int row = blockIdx.x, tid = threadIdx.x;
    const float* p = preds + (size_t)row*VOCAB;
    float m = -1e30f, s = 0.f;
    for (int v = tid; v < VOCAB; v += 256) {
        float x = p[v];
        if (x <= m) s += __expf(x - m);
        else { s = s*__expf(m - x) + 1.f; m = x; }
    }
    #pragma unroll
    for (int o = 16; o; o >>= 1) {
        float mo = __shfl_xor_sync(~0u, m, o);
        float so = __shfl_xor_sync(~0u, s, o);
        float nm = fmaxf(m, mo);
        s = s*__expf(m - nm) + so*__expf(mo - nm);
        m = nm;
    }
    if ((tid & 31) == 0) { rm[tid >> 5] = m; rs[tid >> 5] = s; }
    __syncthreads();
    if (tid == 0) {
        float M = rm[0], S = rs[0];
        for (int w = 1; w < 8; w++) {
            float nm = fmaxf(M, rm[w]);
            S = S*__expf(M - nm) + rs[w]*__expf(rm[w] - nm);
            M = nm;
        }
        int tgt = yout[row];
        float msk = (tgt != 0) ? 1.f : 0.f;
        g_nll[row] = (M + logf(S) - p[tgt]) * msk;
        g_msk[row] = msk;
    }
}

// ---- launch 8: final loss reduce ----
__global__ void k_loss_final(float* __restrict__ out, int oi) {
    __shared__ float ra[8], rb[8];
    int tid = threadIdx.x;
    float a = 0.f, b = 0.f;
    for (int r = tid; r < ROWS_TOT; r += 256) { a += g_nll[r]; b += g_msk[r]; }
    #pragma unroll
    for (int o = 16; o; o >>= 1) { a += __shfl_xor_sync(~0u, a, o); b += __shfl_xor_sync(~0u, b, o); }
    if ((tid & 31) == 0) { ra[tid >> 5] = a; rb[tid >> 5] = b; }
    __syncthreads();
    if (tid == 0) {
        float sa = 0.f, sb = 0.f;
        for (int w = 0; w < 8; w++) { sa += ra[w]; sb += rb[w]; }
        out[oi] = sa / fmaxf(sb, 1.f);
    }
}

extern "C" void kernel_launch(void* const* d_in, const int* in_sizes, int n_in,
                              void* d_out, int out_size) {
    const int*   y_in  = (const int*)  d_in[0];
    const int*   y_out = (const int*)  d_in[1];
    const float* y_enc = (const float*)d_in[2];
    const float* emb   = (const float*)d_in[4];
    const float* f1_w1 = (const float*)d_in[5];
    const float* f1_b1 = (const float*)d_in[6];
    const float* f1_w2 = (const float*)d_in[7];
    const float* f1_b2 = (const float*)d_in[8];
    const float* f2_w1 = (const float*)d_in[9];
    const float* f2_b1 = (const float*)d_in[10];
    const float* f2_w2 = (const float*)d_in[11];
    const float* f2_b2 = (const float*)d_in[12];
    const float* g_wih = (const float*)d_in[13];
    const float* g_bih = (const float*)d_in[14];
    const float* g_whh = (const float*)d_in[15];
    const float* g_bhh = (const float*)d_in[16];
    const float* fc1_w = (const float*)d_in[17];
    const float* fc1_b = (const float*)d_in[18];
    const float* fc2_w = (const float*)d_in[19];
    const float* fc2_b = (const float*)d_in[20];

    float* preds = (float*)d_out;
    const long long TBV = (long long)TS*BB*VOCAB;

    cudaFuncSetAttribute(k_loop, cudaFuncAttributeMaxDynamicSharedMemorySize, 98304);

    k_prep<<<289, 256>>>(f2_w1, f2_w2, f1_w2, fc1_w, y_in, emb);          // 1
    k_tr_fc2<<<dim3(8, 1000), 256>>>(fc2_w);                               // 2
    k_c2<<<(SQ*BB)/16, 256>>>(y_enc, f2_b1, f2_b2);                        // 3
    k_loop<<<NB, 256, 98304>>>(y_enc, g_wih, g_bih, g_whh, g_bhh,
                               f1_w1, f1_b1, f1_b2);                       // 4 <- profiled
    k_fc1<<<ROWS_TOT/16, 256>>>(fc1_b);                                    // 5
    k_fc2<<<dim3(VOCAB/FBN, ROWS_TOT/FBM), 256>>>(fc2_b, preds);           // 6
    if ((long long)out_size >= TBV + 1) {
        k_loss<<<ROWS_TOT, 256>>>(preds, y_out);                           // 7
        k_loss_final<<<1, 256>>>(preds, (int)TBV);                         // 8
    }
}